// round 4
// baseline (speedup 1.0000x reference)
#include <cuda_runtime.h>

#define BB 2
#define SS 2048
#define DD 256
#define HH 8
#define DH 32
#define NROWS (BB*SS)   // 4096

// Scratch (device globals: no allocation allowed)
__device__ float g_q[NROWS*DD];
__device__ float g_k[NROWS*DD];
__device__ float g_v[NROWS*DD];
__device__ float g_ctx[NROWS*DD];
__device__ float g_sqq[NROWS*HH];
__device__ float g_sqk[NROWS*HH];
__device__ float g_wc[DD*DD];
__device__ float g_bc[DD];
__device__ float g_pacc[2*NROWS*DD];   // split-K partial accumulators
__device__ float g_pl[2*NROWS*HH];     // split-K partial softmax sums

typedef unsigned long long u64;

// ---- Blackwell packed f32x2 helpers (FFMA2: 2 fp32 FMAs per instruction) ----
__device__ __forceinline__ u64 ffma2(u64 a, u64 b, u64 c){
    u64 d; asm("fma.rn.f32x2 %0, %1, %2, %3;" : "=l"(d) : "l"(a), "l"(b), "l"(c)); return d;
}
__device__ __forceinline__ u64 fadd2(u64 a, u64 b){
    u64 d; asm("add.rn.f32x2 %0, %1, %2;" : "=l"(d) : "l"(a), "l"(b)); return d;
}
__device__ __forceinline__ u64 pack2(float x, float y){
    u64 r; asm("mov.b64 %0, {%1, %2};" : "=l"(r) : "f"(x), "f"(y)); return r;
}
__device__ __forceinline__ float2 unpack2(u64 a){
    float2 f; asm("mov.b64 {%0, %1}, %2;" : "=f"(f.x), "=f"(f.y) : "l"(a)); return f;
}

// ---------------------------------------------------------------------------
// GEMM body: C[m,n] = sum_k A[m,k] * W[n,k] + bias[n]
// 64x64 tile, 256 threads, 4 rows x 4 cols per thread, K-step 16, FFMA2 inner.
// ---------------------------------------------------------------------------
__device__ __forceinline__ void gemm_body(
    const float* __restrict__ A, const float* __restrict__ W,
    const float* __restrict__ bias, float* __restrict__ C,
    int m0, int n0)
{
    __shared__ __align__(16) float As[16][68];
    __shared__ __align__(16) float Bs[16][68];

    const int tid = threadIdx.x;
    const int lr = tid >> 2;
    const int lv = tid & 3;
    const int tx = tid & 15;
    const int ty = tid >> 4;

    u64 c2[4][2];
    #pragma unroll
    for (int r = 0; r < 4; r++) { c2[r][0] = 0ull; c2[r][1] = 0ull; }

    for (int k0 = 0; k0 < DD; k0 += 16) {
        float4 av = *(const float4*)&A[(m0 + lr) * DD + k0 + lv * 4];
        float4 bv = *(const float4*)&W[(n0 + lr) * DD + k0 + lv * 4];
        __syncthreads();
        As[lv*4+0][lr] = av.x; As[lv*4+1][lr] = av.y;
        As[lv*4+2][lr] = av.z; As[lv*4+3][lr] = av.w;
        Bs[lv*4+0][lr] = bv.x; Bs[lv*4+1][lr] = bv.y;
        Bs[lv*4+2][lr] = bv.z; Bs[lv*4+3][lr] = bv.w;
        __syncthreads();
        #pragma unroll
        for (int kk = 0; kk < 16; kk++) {
            float4 a4 = *(const float4*)&As[kk][ty * 4];
            ulonglong2 bp = *(const ulonglong2*)&Bs[kk][tx * 4];
            u64 a0 = pack2(a4.x, a4.x);
            u64 a1 = pack2(a4.y, a4.y);
            u64 a2 = pack2(a4.z, a4.z);
            u64 a3 = pack2(a4.w, a4.w);
            c2[0][0] = ffma2(a0, bp.x, c2[0][0]); c2[0][1] = ffma2(a0, bp.y, c2[0][1]);
            c2[1][0] = ffma2(a1, bp.x, c2[1][0]); c2[1][1] = ffma2(a1, bp.y, c2[1][1]);
            c2[2][0] = ffma2(a2, bp.x, c2[2][0]); c2[2][1] = ffma2(a2, bp.y, c2[2][1]);
            c2[3][0] = ffma2(a3, bp.x, c2[3][0]); c2[3][1] = ffma2(a3, bp.y, c2[3][1]);
        }
    }

    const int n = n0 + tx * 4;
    float4 bb = *(const float4*)&bias[n];
    #pragma unroll
    for (int r = 0; r < 4; r++) {
        float2 lo = unpack2(c2[r][0]);
        float2 hi = unpack2(c2[r][1]);
        float4 o;
        o.x = lo.x + bb.x; o.y = lo.y + bb.y;
        o.z = hi.x + bb.z; o.w = hi.y + bb.w;
        *(float4*)&C[(m0 + ty*4 + r) * DD + n] = o;
    }
}

// QKV projections fused into one launch: blockIdx.z selects the matrix.
struct QKVArgs {
    const float *Wq, *bq, *Wk, *bk, *Wv, *bv;
    float *q, *k, *v;
};

__global__ __launch_bounds__(256) void gemm_qkv(const float* __restrict__ x, QKVArgs a)
{
    const float* W; const float* b; float* C;
    if (blockIdx.z == 0)      { W = a.Wq; b = a.bq; C = a.q; }
    else if (blockIdx.z == 1) { W = a.Wk; b = a.bk; C = a.k; }
    else                      { W = a.Wv; b = a.bv; C = a.v; }
    gemm_body(x, W, b, C, blockIdx.y * 64, blockIdx.x * 64);
}

__global__ __launch_bounds__(256) void gemm_single(
    const float* __restrict__ A, const float* __restrict__ W,
    const float* __restrict__ bias, float* __restrict__ C)
{
    gemm_body(A, W, bias, C, blockIdx.y * 64, blockIdx.x * 64);
}

// ---------------------------------------------------------------------------
// Wcomb = Wfc @ Wo  (so out = ctx @ Wcomb^T + bcomb, fusing two GEMMs)
// ---------------------------------------------------------------------------
__global__ __launch_bounds__(256) void wcomb_kernel(
    const float* __restrict__ Wfc, const float* __restrict__ Wo,
    float* __restrict__ Wc)
{
    __shared__ float wf[DD];
    const int n = blockIdx.x;
    const int kx = threadIdx.x;
    wf[kx] = Wfc[n * DD + kx];
    __syncthreads();
    float a0 = 0.f, a1 = 0.f, a2 = 0.f, a3 = 0.f;
    #pragma unroll 4
    for (int j = 0; j < DD; j += 4) {
        a0 = fmaf(wf[j+0], Wo[(j+0) * DD + kx], a0);
        a1 = fmaf(wf[j+1], Wo[(j+1) * DD + kx], a1);
        a2 = fmaf(wf[j+2], Wo[(j+2) * DD + kx], a2);
        a3 = fmaf(wf[j+3], Wo[(j+3) * DD + kx], a3);
    }
    Wc[n * DD + kx] = (a0 + a1) + (a2 + a3);
}

__global__ __launch_bounds__(256) void bcomb_kernel(
    const float* __restrict__ Wfc, const float* __restrict__ bo,
    const float* __restrict__ bfc, float* __restrict__ bc)
{
    const int n = threadIdx.x;
    float acc = bfc[n];
    for (int j = 0; j < DD; j++) acc = fmaf(Wfc[n * DD + j], bo[j], acc);
    bc[n] = acc;
}

// ---------------------------------------------------------------------------
// expmap0 for q and k in one launch (blockIdx.y selects tensor).
// ---------------------------------------------------------------------------
__global__ __launch_bounds__(256) void expmap_kernel(
    float* __restrict__ q, float* __restrict__ k,
    float* __restrict__ sqq, float* __restrict__ sqk)
{
    float* p  = blockIdx.y ? k : q;
    float* sq = blockIdx.y ? sqk : sqq;
    const int row  = blockIdx.x;
    const int h    = threadIdx.x >> 5;
    const int lane = threadIdx.x & 31;
    const int idx  = row * DD + h * DH + lane;
    float v = p[idx];
    float s = v * v;
    #pragma unroll
    for (int o = 16; o; o >>= 1) s += __shfl_xor_sync(0xffffffffu, s, o);
    float n2  = fmaxf(s, 1e-12f);
    float nrm = sqrtf(n2);
    float t   = tanhf(nrm);
    p[idx] = v * (t / nrm);
    if (lane == 0) sq[row * HH + h] = t * t;
}

// ---------------------------------------------------------------------------
// Hyperbolic-distance attention, split-K, 2 query rows per thread.
// Scores in [-2.16, 0] (dist>=0, atanh clipped) => partial sums merge by
// plain addition (no running max).
//   w = exp(-dist/sqrt(32)) = __expf(ALN2 * (log2(den-nn) - log2(den+nn)))
// ---------------------------------------------------------------------------
#define QT 256          /* q rows per block (2 per thread) */
#define KT 128          /* key tile */
#define KSPLIT 2        /* t-range halves */
#define THALF (SS/KSPLIT)
#define ALN2 0.12253226f   /* ln2 / sqrt(32) */

__device__ __forceinline__ float pair_w(float qk, float kk, float qq, float Bq)
{
    float Aq  = (1.0f + kk) - 2.0f * qk;
    float den = fmaf(qq, kk, Aq - kk);            // 1 - 2qk + qq*kk
    float e1  = fmaf(Aq, qq, -(Bq * qk));
    float e2  = fmaf(Bq, kk, -(Aq * qk));
    float num2= fmaf(Aq, e1, Bq * e2);
    num2 = fmaxf(num2, 0.0f);
    den  = fmaxf(den, 1e-12f);
    float nn = num2 * rsqrtf(fmaxf(num2, 1e-38f));  // sqrt(num2)
    float nc = fminf(nn, 0.99999f * den);           // clip n <= 1-1e-5
    return __expf(ALN2 * (__log2f(den - nc) - __log2f(den + nc)));
}

__global__ __launch_bounds__(128) void attn_kernel(
    const float* __restrict__ q, const float* __restrict__ k,
    const float* __restrict__ v, const float* __restrict__ sqq,
    const float* __restrict__ sqk, float* __restrict__ pacc,
    float* __restrict__ pl)
{
    __shared__ __align__(16) float sk[KT][DH];
    __shared__ __align__(16) float sv[KT][DH];
    __shared__ float skk[KT];

    const int b    = blockIdx.z >> 1;
    const int half = blockIdx.z & 1;
    const int h    = blockIdx.y;
    const int s0   = blockIdx.x * QT;
    const int tid  = threadIdx.x;

    const int r0 = b * SS + s0 + tid;          // global row of q-row 0
    const int r1 = r0 + 128;                   // q-row 1

    // load both q rows into packed registers
    u64 qr2[2][16];
    float qq[2], Bq[2];
    #pragma unroll
    for (int rr = 0; rr < 2; rr++) {
        const float* qp = q + ((rr ? r1 : r0) * DD + h * DH);
        #pragma unroll
        for (int j = 0; j < 8; j++) {
            float4 t4 = ((const float4*)qp)[j];
            qr2[rr][2*j]   = pack2(t4.x, t4.y);
            qr2[rr][2*j+1] = pack2(t4.z, t4.w);
        }
        qq[rr] = sqq[(rr ? r1 : r0) * HH + h];
        Bq[rr] = 1.0f - qq[rr];
    }

    u64 acc2[2][16];
    #pragma unroll
    for (int d = 0; d < 16; d++) { acc2[0][d] = 0ull; acc2[1][d] = 0ull; }
    float l0 = 0.0f, l1 = 0.0f;

    const int tbase = half * THALF;
    for (int t0 = tbase; t0 < tbase + THALF; t0 += KT) {
        __syncthreads();
        for (int idx = tid; idx < KT * 8; idx += 128) {
            int t = idx >> 3, j = idx & 7;
            const float* kp = k + ((b * SS + t0 + t) * DD + h * DH);
            const float* vp = v + ((b * SS + t0 + t) * DD + h * DH);
            ((float4*)sk[t])[j] = ((const float4*)kp)[j];
            ((float4*)sv[t])[j] = ((const float4*)vp)[j];
        }
        skk[tid] = sqk[(b * SS + t0 + tid) * HH + h];
        __syncthreads();

        for (int t = 0; t < KT; t++) {
            const ulonglong2* kp2 = (const ulonglong2*)sk[t];
            u64 s00 = 0ull, s01 = 0ull, s10 = 0ull, s11 = 0ull;
            #pragma unroll
            for (int j = 0; j < 8; j++) {
                ulonglong2 kv = kp2[j];
                s00 = ffma2(qr2[0][2*j],   kv.x, s00);
                s01 = ffma2(qr2[0][2*j+1], kv.y, s01);
                s10 = ffma2(qr2[1][2*j],   kv.x, s10);
                s11 = ffma2(qr2[1][2*j+1], kv.y, s11);
            }
            float2 f0 = unpack2(fadd2(s00, s01));
            float2 f1 = unpack2(fadd2(s10, s11));
            float qk0 = f0.x + f0.y;
            float qk1 = f1.x + f1.y;

            float kk = skk[t];
            float w0 = pair_w(qk0, kk, qq[0], Bq[0]);
            float w1 = pair_w(qk1, kk, qq[1], Bq[1]);
            l0 += w0;
            l1 += w1;

            u64 w20 = pack2(w0, w0);
            u64 w21 = pack2(w1, w1);
            const ulonglong2* vp2 = (const ulonglong2*)sv[t];
            #pragma unroll
            for (int j = 0; j < 8; j++) {
                ulonglong2 vv = vp2[j];
                acc2[0][2*j]   = ffma2(w20, vv.x, acc2[0][2*j]);
                acc2[0][2*j+1] = ffma2(w20, vv.y, acc2[0][2*j+1]);
                acc2[1][2*j]   = ffma2(w21, vv.x, acc2[1][2*j]);
                acc2[1][2*j+1] = ffma2(w21, vv.y, acc2[1][2*j+1]);
            }
        }
    }

    // write unnormalized partials
    #pragma unroll
    for (int rr = 0; rr < 2; rr++) {
        const int r = rr ? r1 : r0;
        float* op = pacc + (half * NROWS * DD + r * DD + h * DH);
        #pragma unroll
        for (int j = 0; j < 8; j++) {
            float2 lo = unpack2(acc2[rr][2*j]);
            float2 hi = unpack2(acc2[rr][2*j+1]);
            float4 o; o.x = lo.x; o.y = lo.y; o.z = hi.x; o.w = hi.y;
            ((float4*)op)[j] = o;
        }
        pl[half * NROWS * HH + r * HH + h] = rr ? l1 : l0;
    }
}

// Merge the two split-K halves and normalize.
__global__ __launch_bounds__(256) void combine_kernel(
    const float* __restrict__ pacc, const float* __restrict__ pl,
    float* __restrict__ ctx)
{
    const int row = blockIdx.x;
    const int d   = threadIdx.x;
    const int h   = d >> 5;
    float a = pacc[row * DD + d] + pacc[NROWS * DD + row * DD + d];
    float l = pl[row * HH + h] + pl[NROWS * HH + row * HH + h];
    ctx[row * DD + d] = a * __fdividef(1.0f, l);
}

// ---------------------------------------------------------------------------

extern "C" void kernel_launch(void* const* d_in, const int* in_sizes, int n_in,
                              void* d_out, int out_size)
{
    const float* x   = (const float*)d_in[0];
    const float* Wq  = (const float*)d_in[1];
    const float* bq  = (const float*)d_in[2];
    const float* Wk  = (const float*)d_in[3];
    const float* bk  = (const float*)d_in[4];
    const float* Wv  = (const float*)d_in[5];
    const float* bv  = (const float*)d_in[6];
    const float* Wo  = (const float*)d_in[7];
    const float* bo  = (const float*)d_in[8];
    const float* Wfc = (const float*)d_in[9];
    const float* bfc = (const float*)d_in[10];
    float* out = (float*)d_out;

    float *q, *k, *v, *ctx, *sqq, *sqk, *wc, *bc, *pacc, *pl;
    cudaGetSymbolAddress((void**)&q,    g_q);
    cudaGetSymbolAddress((void**)&k,    g_k);
    cudaGetSymbolAddress((void**)&v,    g_v);
    cudaGetSymbolAddress((void**)&ctx,  g_ctx);
    cudaGetSymbolAddress((void**)&sqq,  g_sqq);
    cudaGetSymbolAddress((void**)&sqk,  g_sqk);
    cudaGetSymbolAddress((void**)&wc,   g_wc);
    cudaGetSymbolAddress((void**)&bc,   g_bc);
    cudaGetSymbolAddress((void**)&pacc, g_pacc);
    cudaGetSymbolAddress((void**)&pl,   g_pl);

    // Combined output weights (fuses Wo and Wfc GEMMs)
    wcomb_kernel<<<DD, DD>>>(Wfc, Wo, wc);
    bcomb_kernel<<<1, DD>>>(Wfc, bo, bfc, bc);

    // Q/K/V projections in one launch
    QKVArgs a { Wq, bq, Wk, bk, Wv, bv, q, k, v };
    dim3 qkvgrid(DD / 64, NROWS / 64, 3);
    gemm_qkv<<<qkvgrid, 256>>>(x, a);

    // expmap0 on q and k (one launch)
    dim3 egrid(NROWS, 2);
    expmap_kernel<<<egrid, 256>>>(q, k, sqq, sqk);

    // attention (split-K over key range, 2 q rows per thread)
    dim3 agrid(SS / QT, HH, BB * KSPLIT);
    attn_kernel<<<agrid, 128>>>(q, k, v, sqq, sqk, pacc, pl);
    combine_kernel<<<NROWS, DD>>>(pacc, pl, ctx);

    // fused output projection + fc
    dim3 ggrid(DD / 64, NROWS / 64);
    gemm_single<<<ggrid, 256>>>(ctx, wc, bc, out);
}

// round 5
// speedup vs baseline: 1.0001x; 1.0001x over previous
#include <cuda_runtime.h>

#define BB 2
#define SS 2048
#define DD 256
#define HH 8
#define DH 32
#define NROWS (BB*SS)   // 4096

// Scratch (device globals: no allocation allowed)
__device__ float g_q[NROWS*DD];
__device__ float g_k[NROWS*DD];
__device__ float g_v[NROWS*DD];
__device__ float g_ctx[NROWS*DD];
__device__ float g_sqq[NROWS*HH];
__device__ float g_sqk[NROWS*HH];
__device__ float g_wc[DD*DD];
__device__ float g_bc[DD];
__device__ float g_pacc[2*NROWS*DD];   // split-K partial accumulators
__device__ float g_pl[2*NROWS*HH];     // split-K partial softmax sums

typedef unsigned long long u64;

// ---- Blackwell packed f32x2 helpers (FFMA2: 2 fp32 FMAs per instruction) ----
__device__ __forceinline__ u64 ffma2(u64 a, u64 b, u64 c){
    u64 d; asm("fma.rn.f32x2 %0, %1, %2, %3;" : "=l"(d) : "l"(a), "l"(b), "l"(c)); return d;
}
__device__ __forceinline__ u64 fadd2(u64 a, u64 b){
    u64 d; asm("add.rn.f32x2 %0, %1, %2;" : "=l"(d) : "l"(a), "l"(b)); return d;
}
__device__ __forceinline__ u64 pack2(float x, float y){
    u64 r; asm("mov.b64 %0, {%1, %2};" : "=l"(r) : "f"(x), "f"(y)); return r;
}
__device__ __forceinline__ float2 unpack2(u64 a){
    float2 f; asm("mov.b64 {%0, %1}, %2;" : "=f"(f.x), "=f"(f.y) : "l"(a)); return f;
}

// ---------------------------------------------------------------------------
// GEMM body: C[m,n] = sum_k A[m,k] * W[n,k] + bias[n]
// 64x64 tile, 256 threads, 4 rows x 4 cols per thread, K-step 16, FFMA2 inner.
// ---------------------------------------------------------------------------
__device__ __forceinline__ void gemm_body(
    const float* __restrict__ A, const float* __restrict__ W,
    const float* __restrict__ bias, float* __restrict__ C,
    int m0, int n0)
{
    __shared__ __align__(16) float As[16][68];
    __shared__ __align__(16) float Bs[16][68];

    const int tid = threadIdx.x;
    const int lr = tid >> 2;
    const int lv = tid & 3;
    const int tx = tid & 15;
    const int ty = tid >> 4;

    u64 c2[4][2];
    #pragma unroll
    for (int r = 0; r < 4; r++) { c2[r][0] = 0ull; c2[r][1] = 0ull; }

    for (int k0 = 0; k0 < DD; k0 += 16) {
        float4 av = *(const float4*)&A[(m0 + lr) * DD + k0 + lv * 4];
        float4 bv = *(const float4*)&W[(n0 + lr) * DD + k0 + lv * 4];
        __syncthreads();
        As[lv*4+0][lr] = av.x; As[lv*4+1][lr] = av.y;
        As[lv*4+2][lr] = av.z; As[lv*4+3][lr] = av.w;
        Bs[lv*4+0][lr] = bv.x; Bs[lv*4+1][lr] = bv.y;
        Bs[lv*4+2][lr] = bv.z; Bs[lv*4+3][lr] = bv.w;
        __syncthreads();
        #pragma unroll
        for (int kk = 0; kk < 16; kk++) {
            float4 a4 = *(const float4*)&As[kk][ty * 4];
            ulonglong2 bp = *(const ulonglong2*)&Bs[kk][tx * 4];
            u64 a0 = pack2(a4.x, a4.x);
            u64 a1 = pack2(a4.y, a4.y);
            u64 a2 = pack2(a4.z, a4.z);
            u64 a3 = pack2(a4.w, a4.w);
            c2[0][0] = ffma2(a0, bp.x, c2[0][0]); c2[0][1] = ffma2(a0, bp.y, c2[0][1]);
            c2[1][0] = ffma2(a1, bp.x, c2[1][0]); c2[1][1] = ffma2(a1, bp.y, c2[1][1]);
            c2[2][0] = ffma2(a2, bp.x, c2[2][0]); c2[2][1] = ffma2(a2, bp.y, c2[2][1]);
            c2[3][0] = ffma2(a3, bp.x, c2[3][0]); c2[3][1] = ffma2(a3, bp.y, c2[3][1]);
        }
    }

    const int n = n0 + tx * 4;
    float4 bb = *(const float4*)&bias[n];
    #pragma unroll
    for (int r = 0; r < 4; r++) {
        float2 lo = unpack2(c2[r][0]);
        float2 hi = unpack2(c2[r][1]);
        float4 o;
        o.x = lo.x + bb.x; o.y = lo.y + bb.y;
        o.z = hi.x + bb.z; o.w = hi.y + bb.w;
        *(float4*)&C[(m0 + ty*4 + r) * DD + n] = o;
    }
}

// QKV projections fused into one launch: blockIdx.z selects the matrix.
struct QKVArgs {
    const float *Wq, *bq, *Wk, *bk, *Wv, *bv;
    float *q, *k, *v;
};

__global__ __launch_bounds__(256) void gemm_qkv(const float* __restrict__ x, QKVArgs a)
{
    const float* W; const float* b; float* C;
    if (blockIdx.z == 0)      { W = a.Wq; b = a.bq; C = a.q; }
    else if (blockIdx.z == 1) { W = a.Wk; b = a.bk; C = a.k; }
    else                      { W = a.Wv; b = a.bv; C = a.v; }
    gemm_body(x, W, b, C, blockIdx.y * 64, blockIdx.x * 64);
}

__global__ __launch_bounds__(256) void gemm_single(
    const float* __restrict__ A, const float* __restrict__ W,
    const float* __restrict__ bias, float* __restrict__ C)
{
    gemm_body(A, W, bias, C, blockIdx.y * 64, blockIdx.x * 64);
}

// ---------------------------------------------------------------------------
// Wcomb = Wfc @ Wo  (so out = ctx @ Wcomb^T + bcomb, fusing two GEMMs)
// ---------------------------------------------------------------------------
__global__ __launch_bounds__(256) void wcomb_kernel(
    const float* __restrict__ Wfc, const float* __restrict__ Wo,
    float* __restrict__ Wc)
{
    __shared__ float wf[DD];
    const int n = blockIdx.x;
    const int kx = threadIdx.x;
    wf[kx] = Wfc[n * DD + kx];
    __syncthreads();
    float a0 = 0.f, a1 = 0.f, a2 = 0.f, a3 = 0.f;
    #pragma unroll 4
    for (int j = 0; j < DD; j += 4) {
        a0 = fmaf(wf[j+0], Wo[(j+0) * DD + kx], a0);
        a1 = fmaf(wf[j+1], Wo[(j+1) * DD + kx], a1);
        a2 = fmaf(wf[j+2], Wo[(j+2) * DD + kx], a2);
        a3 = fmaf(wf[j+3], Wo[(j+3) * DD + kx], a3);
    }
    Wc[n * DD + kx] = (a0 + a1) + (a2 + a3);
}

__global__ __launch_bounds__(256) void bcomb_kernel(
    const float* __restrict__ Wfc, const float* __restrict__ bo,
    const float* __restrict__ bfc, float* __restrict__ bc)
{
    const int n = threadIdx.x;
    float acc = bfc[n];
    for (int j = 0; j < DD; j++) acc = fmaf(Wfc[n * DD + j], bo[j], acc);
    bc[n] = acc;
}

// ---------------------------------------------------------------------------
// expmap0 for q and k in one launch (blockIdx.y selects tensor).
// ---------------------------------------------------------------------------
__global__ __launch_bounds__(256) void expmap_kernel(
    float* __restrict__ q, float* __restrict__ k,
    float* __restrict__ sqq, float* __restrict__ sqk)
{
    float* p  = blockIdx.y ? k : q;
    float* sq = blockIdx.y ? sqk : sqq;
    const int row  = blockIdx.x;
    const int h    = threadIdx.x >> 5;
    const int lane = threadIdx.x & 31;
    const int idx  = row * DD + h * DH + lane;
    float v = p[idx];
    float s = v * v;
    #pragma unroll
    for (int o = 16; o; o >>= 1) s += __shfl_xor_sync(0xffffffffu, s, o);
    float n2  = fmaxf(s, 1e-12f);
    float nrm = sqrtf(n2);
    float t   = tanhf(nrm);
    p[idx] = v * (t / nrm);
    if (lane == 0) sq[row * HH + h] = t * t;
}

// ---------------------------------------------------------------------------
// Hyperbolic-distance attention, split-K, 2 query rows per thread.
// Scores in [-2.16, 0] (dist>=0, atanh clipped) => partial sums merge by
// plain addition (no running max).
//   w = exp(-dist/sqrt(32)) = __expf(ALN2 * (log2(den-nn) - log2(den+nn)))
// ---------------------------------------------------------------------------
#define QT 256          /* q rows per block (2 per thread) */
#define KT 128          /* key tile */
#define KSPLIT 2        /* t-range halves */
#define THALF (SS/KSPLIT)
#define ALN2 0.12253226f   /* ln2 / sqrt(32) */

__device__ __forceinline__ float pair_w(float qk, float kk, float qq, float Bq)
{
    float Aq  = (1.0f + kk) - 2.0f * qk;
    float den = fmaf(qq, kk, Aq - kk);            // 1 - 2qk + qq*kk
    float e1  = fmaf(Aq, qq, -(Bq * qk));
    float e2  = fmaf(Bq, kk, -(Aq * qk));
    float num2= fmaf(Aq, e1, Bq * e2);
    num2 = fmaxf(num2, 0.0f);
    den  = fmaxf(den, 1e-12f);
    float nn = num2 * rsqrtf(fmaxf(num2, 1e-38f));  // sqrt(num2)
    float nc = fminf(nn, 0.99999f * den);           // clip n <= 1-1e-5
    return __expf(ALN2 * (__log2f(den - nc) - __log2f(den + nc)));
}

__global__ __launch_bounds__(128) void attn_kernel(
    const float* __restrict__ q, const float* __restrict__ k,
    const float* __restrict__ v, const float* __restrict__ sqq,
    const float* __restrict__ sqk, float* __restrict__ pacc,
    float* __restrict__ pl)
{
    __shared__ __align__(16) float sk[KT][DH];
    __shared__ __align__(16) float sv[KT][DH];
    __shared__ float skk[KT];

    const int b    = blockIdx.z >> 1;
    const int half = blockIdx.z & 1;
    const int h    = blockIdx.y;
    const int s0   = blockIdx.x * QT;
    const int tid  = threadIdx.x;

    const int r0 = b * SS + s0 + tid;          // global row of q-row 0
    const int r1 = r0 + 128;                   // q-row 1

    // load both q rows into packed registers
    u64 qr2[2][16];
    float qq[2], Bq[2];
    #pragma unroll
    for (int rr = 0; rr < 2; rr++) {
        const float* qp = q + ((rr ? r1 : r0) * DD + h * DH);
        #pragma unroll
        for (int j = 0; j < 8; j++) {
            float4 t4 = ((const float4*)qp)[j];
            qr2[rr][2*j]   = pack2(t4.x, t4.y);
            qr2[rr][2*j+1] = pack2(t4.z, t4.w);
        }
        qq[rr] = sqq[(rr ? r1 : r0) * HH + h];
        Bq[rr] = 1.0f - qq[rr];
    }

    u64 acc2[2][16];
    #pragma unroll
    for (int d = 0; d < 16; d++) { acc2[0][d] = 0ull; acc2[1][d] = 0ull; }
    float l0 = 0.0f, l1 = 0.0f;

    const int tbase = half * THALF;
    for (int t0 = tbase; t0 < tbase + THALF; t0 += KT) {
        __syncthreads();
        for (int idx = tid; idx < KT * 8; idx += 128) {
            int t = idx >> 3, j = idx & 7;
            const float* kp = k + ((b * SS + t0 + t) * DD + h * DH);
            const float* vp = v + ((b * SS + t0 + t) * DD + h * DH);
            ((float4*)sk[t])[j] = ((const float4*)kp)[j];
            ((float4*)sv[t])[j] = ((const float4*)vp)[j];
        }
        skk[tid] = sqk[(b * SS + t0 + tid) * HH + h];
        __syncthreads();

        for (int t = 0; t < KT; t++) {
            const ulonglong2* kp2 = (const ulonglong2*)sk[t];
            u64 s00 = 0ull, s01 = 0ull, s10 = 0ull, s11 = 0ull;
            #pragma unroll
            for (int j = 0; j < 8; j++) {
                ulonglong2 kv = kp2[j];
                s00 = ffma2(qr2[0][2*j],   kv.x, s00);
                s01 = ffma2(qr2[0][2*j+1], kv.y, s01);
                s10 = ffma2(qr2[1][2*j],   kv.x, s10);
                s11 = ffma2(qr2[1][2*j+1], kv.y, s11);
            }
            float2 f0 = unpack2(fadd2(s00, s01));
            float2 f1 = unpack2(fadd2(s10, s11));
            float qk0 = f0.x + f0.y;
            float qk1 = f1.x + f1.y;

            float kk = skk[t];
            float w0 = pair_w(qk0, kk, qq[0], Bq[0]);
            float w1 = pair_w(qk1, kk, qq[1], Bq[1]);
            l0 += w0;
            l1 += w1;

            u64 w20 = pack2(w0, w0);
            u64 w21 = pack2(w1, w1);
            const ulonglong2* vp2 = (const ulonglong2*)sv[t];
            #pragma unroll
            for (int j = 0; j < 8; j++) {
                ulonglong2 vv = vp2[j];
                acc2[0][2*j]   = ffma2(w20, vv.x, acc2[0][2*j]);
                acc2[0][2*j+1] = ffma2(w20, vv.y, acc2[0][2*j+1]);
                acc2[1][2*j]   = ffma2(w21, vv.x, acc2[1][2*j]);
                acc2[1][2*j+1] = ffma2(w21, vv.y, acc2[1][2*j+1]);
            }
        }
    }

    // write unnormalized partials
    #pragma unroll
    for (int rr = 0; rr < 2; rr++) {
        const int r = rr ? r1 : r0;
        float* op = pacc + (half * NROWS * DD + r * DD + h * DH);
        #pragma unroll
        for (int j = 0; j < 8; j++) {
            float2 lo = unpack2(acc2[rr][2*j]);
            float2 hi = unpack2(acc2[rr][2*j+1]);
            float4 o; o.x = lo.x; o.y = lo.y; o.z = hi.x; o.w = hi.y;
            ((float4*)op)[j] = o;
        }
        pl[half * NROWS * HH + r * HH + h] = rr ? l1 : l0;
    }
}

// Merge the two split-K halves and normalize.
__global__ __launch_bounds__(256) void combine_kernel(
    const float* __restrict__ pacc, const float* __restrict__ pl,
    float* __restrict__ ctx)
{
    const int row = blockIdx.x;
    const int d   = threadIdx.x;
    const int h   = d >> 5;
    float a = pacc[row * DD + d] + pacc[NROWS * DD + row * DD + d];
    float l = pl[row * HH + h] + pl[NROWS * HH + row * HH + h];
    ctx[row * DD + d] = a * __fdividef(1.0f, l);
}

// ---------------------------------------------------------------------------

extern "C" void kernel_launch(void* const* d_in, const int* in_sizes, int n_in,
                              void* d_out, int out_size)
{
    const float* x   = (const float*)d_in[0];
    const float* Wq  = (const float*)d_in[1];
    const float* bq  = (const float*)d_in[2];
    const float* Wk  = (const float*)d_in[3];
    const float* bk  = (const float*)d_in[4];
    const float* Wv  = (const float*)d_in[5];
    const float* bv  = (const float*)d_in[6];
    const float* Wo  = (const float*)d_in[7];
    const float* bo  = (const float*)d_in[8];
    const float* Wfc = (const float*)d_in[9];
    const float* bfc = (const float*)d_in[10];
    float* out = (float*)d_out;

    float *q, *k, *v, *ctx, *sqq, *sqk, *wc, *bc, *pacc, *pl;
    cudaGetSymbolAddress((void**)&q,    g_q);
    cudaGetSymbolAddress((void**)&k,    g_k);
    cudaGetSymbolAddress((void**)&v,    g_v);
    cudaGetSymbolAddress((void**)&ctx,  g_ctx);
    cudaGetSymbolAddress((void**)&sqq,  g_sqq);
    cudaGetSymbolAddress((void**)&sqk,  g_sqk);
    cudaGetSymbolAddress((void**)&wc,   g_wc);
    cudaGetSymbolAddress((void**)&bc,   g_bc);
    cudaGetSymbolAddress((void**)&pacc, g_pacc);
    cudaGetSymbolAddress((void**)&pl,   g_pl);

    // Combined output weights (fuses Wo and Wfc GEMMs)
    wcomb_kernel<<<DD, DD>>>(Wfc, Wo, wc);
    bcomb_kernel<<<1, DD>>>(Wfc, bo, bfc, bc);

    // Q/K/V projections in one launch
    QKVArgs a { Wq, bq, Wk, bk, Wv, bv, q, k, v };
    dim3 qkvgrid(DD / 64, NROWS / 64, 3);
    gemm_qkv<<<qkvgrid, 256>>>(x, a);

    // expmap0 on q and k (one launch)
    dim3 egrid(NROWS, 2);
    expmap_kernel<<<egrid, 256>>>(q, k, sqq, sqk);

    // attention (split-K over key range, 2 q rows per thread)
    dim3 agrid(SS / QT, HH, BB * KSPLIT);
    attn_kernel<<<agrid, 128>>>(q, k, v, sqq, sqk, pacc, pl);
    combine_kernel<<<NROWS, DD>>>(pacc, pl, ctx);

    // fused output projection + fc
    dim3 ggrid(DD / 64, NROWS / 64);
    gemm_single<<<ggrid, 256>>>(ctx, wc, bc, out);
}

// round 6
// speedup vs baseline: 1.7868x; 1.7867x over previous
#include <cuda_runtime.h>
#include <cstdint>

#define BB 2
#define SS 2048
#define DD 256
#define HH 8
#define DH 32
#define NROWS (BB*SS)   // 4096

// Scratch (device globals: no allocation allowed)
__device__ float g_q[NROWS*DD];
__device__ float g_k[NROWS*DD];
__device__ float g_v[NROWS*DD];
__device__ float g_ctx[NROWS*DD];
__device__ float2 g_sq[2*NROWS*HH];  // {tanh^2, cosh^2}: [0..)=q rows, [NROWS*HH..)=k rows
__device__ float g_wc[DD*DD];
__device__ float g_bc[DD];

typedef unsigned long long u64;

// ---- Blackwell packed f32x2 helpers ----
__device__ __forceinline__ u64 ffma2(u64 a, u64 b, u64 c){
    u64 d; asm("fma.rn.f32x2 %0, %1, %2, %3;" : "=l"(d) : "l"(a), "l"(b), "l"(c)); return d;
}
__device__ __forceinline__ u64 pack2(float x, float y){
    u64 r; asm("mov.b64 %0, {%1, %2};" : "=l"(r) : "f"(x), "f"(y)); return r;
}
__device__ __forceinline__ float2 unpack2(u64 a){
    float2 f; asm("mov.b64 {%0, %1}, %2;" : "=f"(f.x), "=f"(f.y) : "l"(a)); return f;
}

// ---- tf32 / mma helpers ----
__device__ __forceinline__ uint32_t f2tf(float x){
    uint32_t r; asm("cvt.rna.tf32.f32 %0, %1;" : "=r"(r) : "f"(x)); return r;
}
__device__ __forceinline__ void tf32pair(float x, uint32_t& hi, uint32_t& lo){
    hi = f2tf(x);
    lo = f2tf(x - __uint_as_float(hi));
}
__device__ __forceinline__ void mma_tf32(float (&c)[4], const uint32_t (&a)[4], const uint32_t (&b)[2]){
    asm volatile("mma.sync.aligned.m16n8k8.row.col.f32.tf32.tf32.f32 "
        "{%0,%1,%2,%3}, {%4,%5,%6,%7}, {%8,%9}, {%0,%1,%2,%3};"
        : "+f"(c[0]), "+f"(c[1]), "+f"(c[2]), "+f"(c[3])
        : "r"(a[0]), "r"(a[1]), "r"(a[2]), "r"(a[3]), "r"(b[0]), "r"(b[1]));
}
__device__ __forceinline__ float ex2(float x){
    float r; asm("ex2.approx.f32 %0, %1;" : "=f"(r) : "f"(x)); return r;
}

// ---------------------------------------------------------------------------
// SIMT fp32 GEMM (proven): C[m,n] = sum_k A[m,k]*W[n,k] + bias[n]
// ---------------------------------------------------------------------------
__device__ __forceinline__ void gemm_body(
    const float* __restrict__ A, const float* __restrict__ W,
    const float* __restrict__ bias, float* __restrict__ C,
    int m0, int n0)
{
    __shared__ __align__(16) float As[16][68];
    __shared__ __align__(16) float Bs[16][68];

    const int tid = threadIdx.x;
    const int lr = tid >> 2;
    const int lv = tid & 3;
    const int tx = tid & 15;
    const int ty = tid >> 4;

    u64 c2[4][2];
    #pragma unroll
    for (int r = 0; r < 4; r++) { c2[r][0] = 0ull; c2[r][1] = 0ull; }

    for (int k0 = 0; k0 < DD; k0 += 16) {
        float4 av = *(const float4*)&A[(m0 + lr) * DD + k0 + lv * 4];
        float4 bv = *(const float4*)&W[(n0 + lr) * DD + k0 + lv * 4];
        __syncthreads();
        As[lv*4+0][lr] = av.x; As[lv*4+1][lr] = av.y;
        As[lv*4+2][lr] = av.z; As[lv*4+3][lr] = av.w;
        Bs[lv*4+0][lr] = bv.x; Bs[lv*4+1][lr] = bv.y;
        Bs[lv*4+2][lr] = bv.z; Bs[lv*4+3][lr] = bv.w;
        __syncthreads();
        #pragma unroll
        for (int kk = 0; kk < 16; kk++) {
            float4 a4 = *(const float4*)&As[kk][ty * 4];
            ulonglong2 bp = *(const ulonglong2*)&Bs[kk][tx * 4];
            u64 a0 = pack2(a4.x, a4.x);
            u64 a1 = pack2(a4.y, a4.y);
            u64 a2 = pack2(a4.z, a4.z);
            u64 a3 = pack2(a4.w, a4.w);
            c2[0][0] = ffma2(a0, bp.x, c2[0][0]); c2[0][1] = ffma2(a0, bp.y, c2[0][1]);
            c2[1][0] = ffma2(a1, bp.x, c2[1][0]); c2[1][1] = ffma2(a1, bp.y, c2[1][1]);
            c2[2][0] = ffma2(a2, bp.x, c2[2][0]); c2[2][1] = ffma2(a2, bp.y, c2[2][1]);
            c2[3][0] = ffma2(a3, bp.x, c2[3][0]); c2[3][1] = ffma2(a3, bp.y, c2[3][1]);
        }
    }

    const int n = n0 + tx * 4;
    float4 bb = *(const float4*)&bias[n];
    #pragma unroll
    for (int r = 0; r < 4; r++) {
        float2 lo = unpack2(c2[r][0]);
        float2 hi = unpack2(c2[r][1]);
        float4 o;
        o.x = lo.x + bb.x; o.y = lo.y + bb.y;
        o.z = hi.x + bb.z; o.w = hi.y + bb.w;
        *(float4*)&C[(m0 + ty*4 + r) * DD + n] = o;
    }
}

struct QKVArgs {
    const float *Wq, *bq, *Wk, *bk, *Wv, *bv;
    float *q, *k, *v;
};

__global__ __launch_bounds__(256) void gemm_qkv(const float* __restrict__ x, QKVArgs a)
{
    const float* W; const float* b; float* C;
    if (blockIdx.z == 0)      { W = a.Wq; b = a.bq; C = a.q; }
    else if (blockIdx.z == 1) { W = a.Wk; b = a.bk; C = a.k; }
    else                      { W = a.Wv; b = a.bv; C = a.v; }
    gemm_body(x, W, b, C, blockIdx.y * 64, blockIdx.x * 64);
}

__global__ __launch_bounds__(256) void gemm_single(
    const float* __restrict__ A, const float* __restrict__ W,
    const float* __restrict__ bias, float* __restrict__ C)
{
    gemm_body(A, W, bias, C, blockIdx.y * 64, blockIdx.x * 64);
}

// ---------------------------------------------------------------------------
// Wcomb = Wfc @ Wo, bcomb = Wfc @ bo + bfc  (fuses the two output GEMMs)
// ---------------------------------------------------------------------------
__global__ __launch_bounds__(256) void wcomb_kernel(
    const float* __restrict__ Wfc, const float* __restrict__ Wo,
    float* __restrict__ Wc)
{
    __shared__ float wf[DD];
    const int n = blockIdx.x;
    const int kx = threadIdx.x;
    wf[kx] = Wfc[n * DD + kx];
    __syncthreads();
    float a0 = 0.f, a1 = 0.f, a2 = 0.f, a3 = 0.f;
    #pragma unroll 4
    for (int j = 0; j < DD; j += 4) {
        a0 = fmaf(wf[j+0], Wo[(j+0) * DD + kx], a0);
        a1 = fmaf(wf[j+1], Wo[(j+1) * DD + kx], a1);
        a2 = fmaf(wf[j+2], Wo[(j+2) * DD + kx], a2);
        a3 = fmaf(wf[j+3], Wo[(j+3) * DD + kx], a3);
    }
    Wc[n * DD + kx] = (a0 + a1) + (a2 + a3);
}

__global__ __launch_bounds__(256) void bcomb_kernel(
    const float* __restrict__ Wfc, const float* __restrict__ bo,
    const float* __restrict__ bfc, float* __restrict__ bc)
{
    const int n = threadIdx.x;
    float acc = bfc[n];
    for (int j = 0; j < DD; j++) acc = fmaf(Wfc[n * DD + j], bo[j], acc);
    bc[n] = acc;
}

// ---------------------------------------------------------------------------
// expmap0 for q and k (blockIdx.y selects tensor). Writes {tanh^2, cosh^2}.
// ---------------------------------------------------------------------------
__global__ __launch_bounds__(256) void expmap_kernel(
    float* __restrict__ q, float* __restrict__ k, float2* __restrict__ sq)
{
    float* p   = blockIdx.y ? k : q;
    float2* so = sq + blockIdx.y * (NROWS*HH);
    const int row  = blockIdx.x;
    const int h    = threadIdx.x >> 5;
    const int lane = threadIdx.x & 31;
    const int idx  = row * DD + h * DH + lane;
    float v = p[idx];
    float s = v * v;
    #pragma unroll
    for (int o = 16; o; o >>= 1) s += __shfl_xor_sync(0xffffffffu, s, o);
    float n2  = fmaxf(s, 1e-12f);
    float nrm = sqrtf(n2);
    float t   = tanhf(nrm);
    p[idx] = v * (t / nrm);
    if (lane == 0) {
        float ch = coshf(nrm);
        so[row * HH + h] = make_float2(t * t, ch * ch);
    }
}

// ---------------------------------------------------------------------------
// Attention via mma.sync tf32.
//   cosh(dist) = u = 1 + (qq + kk - 2 qk) * (2 * ch2_q * ch2_k)
//   g = u + sqrt(u^2-1) = e^dist, clip: g <= GMAX  <=>  u >= UCLIP -> w = WCLIP
//   w = g^(-1/sqrt(32));  clip is a min() so it's continuous in u.
// Scores in [-2.158, 0] => plain sum softmax (no running max).
// Block = 4 warps x 32 q rows = 128 q rows; keys tiled 64 (two 32-halves).
// S: 1-pass tf32 (clip margin ~1e3x dwarfs tf32 error); PV: V split hi/lo
// (P's tf32 quantization is common-mode and cancels in softmax).
// ---------------------------------------------------------------------------
#define KT 64
#define SC_EXP 0.17677669529663689f   /* 1/sqrt(32) */
#define UCLIP  99999.5f               /* cosh(dist_max), dist_max=2 atanh(1-1e-5) */
#define WCLIP  0.11558618f            /* exp(-dist_max/sqrt(32)) */

__global__ __launch_bounds__(128) void attn_kernel(
    const float* __restrict__ q, const float* __restrict__ k,
    const float* __restrict__ v, const float2* __restrict__ sq2,
    float* __restrict__ ctx)
{
    __shared__ __align__(16) float sK[KT][40];
    __shared__ __align__(16) float sV[KT][40];
    __shared__ __align__(8)  float sP[128][34];
    __shared__ float2 sKC[KT];

    const int b   = blockIdx.z;
    const int h   = blockIdx.y;
    const int q0  = blockIdx.x * 128;
    const int tid = threadIdx.x;
    const int w   = tid >> 5;
    const int lane= tid & 31;
    const int g   = lane >> 2;
    const int t4  = lane & 3;
    const int wrow = w * 32;

    const float2* cq = sq2;               // q-side {tanh^2, cosh^2}
    const float2* ck = sq2 + NROWS*HH;    // k-side

    // per-thread row constants (rows wrow + m*16 + rh*8 + g)
    float qqr[4], fr2[4];
    #pragma unroll
    for (int m = 0; m < 2; m++)
        #pragma unroll
        for (int rh = 0; rh < 2; rh++) {
            int r = b*SS + q0 + wrow + m*16 + rh*8 + g;
            float2 c = cq[r*HH + h];
            qqr[m*2+rh] = c.x;
            fr2[m*2+rh] = 2.0f * c.y;
        }

    // Q fragments (1-pass tf32), persistent across all key tiles
    uint32_t qh[2][4][4];
    #pragma unroll
    for (int m = 0; m < 2; m++)
        #pragma unroll
        for (int ks = 0; ks < 4; ks++) {
            int r0 = b*SS + q0 + wrow + m*16 + g;
            int c0 = h*DH + ks*8 + t4;
            qh[m][ks][0] = f2tf(q[r0*DD + c0]);
            qh[m][ks][1] = f2tf(q[(r0+8)*DD + c0]);
            qh[m][ks][2] = f2tf(q[r0*DD + c0 + 4]);
            qh[m][ks][3] = f2tf(q[(r0+8)*DD + c0 + 4]);
        }

    float O[2][4][4];
    #pragma unroll
    for (int m = 0; m < 2; m++)
        #pragma unroll
        for (int nt = 0; nt < 4; nt++)
            #pragma unroll
            for (int r = 0; r < 4; r++) O[m][nt][r] = 0.0f;
    float lacc[4] = {0.f, 0.f, 0.f, 0.f};

    #pragma unroll 1
    for (int t0 = 0; t0 < SS; t0 += KT) {
        __syncthreads();
        #pragma unroll
        for (int i = 0; i < 4; i++) {
            int l = tid + i*128;          // 0..511
            int row = l >> 3, j = l & 7;
            *(float4*)&sK[row][j*4] = *(const float4*)&k[(b*SS+t0+row)*DD + h*DH + j*4];
            *(float4*)&sV[row][j*4] = *(const float4*)&v[(b*SS+t0+row)*DD + h*DH + j*4];
        }
        if (tid < KT) sKC[tid] = ck[(b*SS + t0 + tid)*HH + h];
        __syncthreads();

        #pragma unroll 1
        for (int half = 0; half < 2; half++) {
            // ---- S = Q K^T for keys [half*32, half*32+32) ----
            float S[2][4][4];
            #pragma unroll
            for (int m = 0; m < 2; m++)
                #pragma unroll
                for (int nt = 0; nt < 4; nt++)
                    #pragma unroll
                    for (int r = 0; r < 4; r++) S[m][nt][r] = 0.0f;

            #pragma unroll
            for (int nt = 0; nt < 4; nt++) {
                int kr = half*32 + nt*8 + g;
                #pragma unroll
                for (int ks = 0; ks < 4; ks++) {
                    uint32_t bh[2];
                    bh[0] = f2tf(sK[kr][ks*8 + t4]);
                    bh[1] = f2tf(sK[kr][ks*8 + t4 + 4]);
                    mma_tf32(S[0][nt], qh[0][ks], bh);
                    mma_tf32(S[1][nt], qh[1][ks], bh);
                }
            }

            // ---- qk -> softmax weight (clip fast path: no MUFU) ----
            #pragma unroll
            for (int m = 0; m < 2; m++)
                #pragma unroll
                for (int nt = 0; nt < 4; nt++)
                    #pragma unroll
                    for (int r = 0; r < 4; r++) {
                        int col  = half*32 + nt*8 + 2*t4 + (r & 1);
                        int ridx = m*2 + (r >> 1);
                        float2 kc = sKC[col];
                        float nm = fmaf(-2.0f, S[m][nt][r], qqr[ridx] + kc.x);
                        float u  = fmaf(nm, fr2[ridx] * kc.y, 1.0f);
                        float w_ = WCLIP;
                        if (u < UCLIP) {
                            float t = fmaf(u, u, -1.0f);
                            t = fmaxf(t, 0.0f);
                            float gg = u + t * rsqrtf(fmaxf(t, 1e-30f));
                            gg = fmaxf(gg, 1.0f);
                            w_ = ex2(-SC_EXP * __log2f(gg));
                        }
                        lacc[ridx] += w_;
                        S[m][nt][r] = w_;
                    }

            // ---- P roundtrip through smem (own warp's rows only) ----
            #pragma unroll
            for (int m = 0; m < 2; m++)
                #pragma unroll
                for (int nt = 0; nt < 4; nt++) {
                    int pr = wrow + m*16 + g;
                    *(float2*)&sP[pr][nt*8 + 2*t4]   = make_float2(S[m][nt][0], S[m][nt][1]);
                    *(float2*)&sP[pr+8][nt*8 + 2*t4] = make_float2(S[m][nt][2], S[m][nt][3]);
                }
            __syncwarp();

            // ---- O += P V  (P 1-pass, V hi+lo) ----
            #pragma unroll
            for (int ks = 0; ks < 4; ks++) {
                uint32_t ah[2][4];
                #pragma unroll
                for (int m = 0; m < 2; m++) {
                    int pr = wrow + m*16 + g;
                    ah[m][0] = f2tf(sP[pr][ks*8 + t4]);
                    ah[m][1] = f2tf(sP[pr+8][ks*8 + t4]);
                    ah[m][2] = f2tf(sP[pr][ks*8 + t4 + 4]);
                    ah[m][3] = f2tf(sP[pr+8][ks*8 + t4 + 4]);
                }
                int kb = half*32 + ks*8;
                #pragma unroll
                for (int nt = 0; nt < 4; nt++) {
                    uint32_t bh[2], bl[2];
                    tf32pair(sV[kb + t4][nt*8 + g],     bh[0], bl[0]);
                    tf32pair(sV[kb + t4 + 4][nt*8 + g], bh[1], bl[1]);
                    mma_tf32(O[0][nt], ah[0], bh);
                    mma_tf32(O[0][nt], ah[0], bl);
                    mma_tf32(O[1][nt], ah[1], bh);
                    mma_tf32(O[1][nt], ah[1], bl);
                }
            }
            __syncwarp();
        }
    }

    // ---- epilogue: reduce l over quad, normalize, store ----
    #pragma unroll
    for (int i = 0; i < 4; i++) {
        lacc[i] += __shfl_xor_sync(0xffffffffu, lacc[i], 1);
        lacc[i] += __shfl_xor_sync(0xffffffffu, lacc[i], 2);
        lacc[i] = __fdividef(1.0f, lacc[i]);
    }
    #pragma unroll
    for (int m = 0; m < 2; m++)
        #pragma unroll
        for (int rh = 0; rh < 2; rh++) {
            int grow = b*SS + q0 + wrow + m*16 + rh*8 + g;
            float rl = lacc[m*2 + rh];
            #pragma unroll
            for (int nt = 0; nt < 4; nt++) {
                float2 o;
                o.x = O[m][nt][rh*2 + 0] * rl;
                o.y = O[m][nt][rh*2 + 1] * rl;
                *(float2*)&ctx[grow*DD + h*DH + nt*8 + 2*t4] = o;
            }
        }
}

// ---------------------------------------------------------------------------

extern "C" void kernel_launch(void* const* d_in, const int* in_sizes, int n_in,
                              void* d_out, int out_size)
{
    const float* x   = (const float*)d_in[0];
    const float* Wq  = (const float*)d_in[1];
    const float* bq  = (const float*)d_in[2];
    const float* Wk  = (const float*)d_in[3];
    const float* bk  = (const float*)d_in[4];
    const float* Wv  = (const float*)d_in[5];
    const float* bv  = (const float*)d_in[6];
    const float* Wo  = (const float*)d_in[7];
    const float* bo  = (const float*)d_in[8];
    const float* Wfc = (const float*)d_in[9];
    const float* bfc = (const float*)d_in[10];
    float* out = (float*)d_out;

    float *q, *k, *v, *ctx, *wc, *bc;
    float2* sq;
    cudaGetSymbolAddress((void**)&q,   g_q);
    cudaGetSymbolAddress((void**)&k,   g_k);
    cudaGetSymbolAddress((void**)&v,   g_v);
    cudaGetSymbolAddress((void**)&ctx, g_ctx);
    cudaGetSymbolAddress((void**)&sq,  g_sq);
    cudaGetSymbolAddress((void**)&wc,  g_wc);
    cudaGetSymbolAddress((void**)&bc,  g_bc);

    // Combined output weights (fuses Wo and Wfc GEMMs)
    wcomb_kernel<<<DD, DD>>>(Wfc, Wo, wc);
    bcomb_kernel<<<1, DD>>>(Wfc, bo, bfc, bc);

    // Q/K/V projections in one launch
    QKVArgs a { Wq, bq, Wk, bk, Wv, bv, q, k, v };
    dim3 qkvgrid(DD / 64, NROWS / 64, 3);
    gemm_qkv<<<qkvgrid, 256>>>(x, a);

    // expmap0 on q and k
    dim3 egrid(NROWS, 2);
    expmap_kernel<<<egrid, 256>>>(q, k, sq);

    // attention (tf32 mma)
    dim3 agrid(SS / 128, HH, BB);
    attn_kernel<<<agrid, 128>>>(q, k, v, sq, ctx);

    // fused output projection + fc
    dim3 ggrid(DD / 64, NROWS / 64);
    gemm_single<<<ggrid, 256>>>(ctx, wc, bc, out);
}

// round 7
// speedup vs baseline: 1.8594x; 1.0407x over previous
#include <cuda_runtime.h>
#include <cstdint>

#define BB 2
#define SS 2048
#define DD 256
#define HH 8
#define DH 32
#define NROWS (BB*SS)   // 4096

// Scratch (device globals: no allocation allowed)
__device__ float g_q[NROWS*DD];
__device__ float g_k[NROWS*DD];
__device__ float g_v[NROWS*DD];
__device__ float g_ctx[NROWS*DD];
__device__ float2 g_sq[2*NROWS*HH];  // {tanh^2, cosh^2}: [0..)=q rows, [NROWS*HH..)=k rows
__device__ float g_wc[DD*DD];
__device__ float g_bc[DD];

typedef unsigned long long u64;

// ---- Blackwell packed f32x2 helpers ----
__device__ __forceinline__ u64 ffma2(u64 a, u64 b, u64 c){
    u64 d; asm("fma.rn.f32x2 %0, %1, %2, %3;" : "=l"(d) : "l"(a), "l"(b), "l"(c)); return d;
}
__device__ __forceinline__ u64 pack2(float x, float y){
    u64 r; asm("mov.b64 %0, {%1, %2};" : "=l"(r) : "f"(x), "f"(y)); return r;
}
__device__ __forceinline__ float2 unpack2(u64 a){
    float2 f; asm("mov.b64 {%0, %1}, %2;" : "=f"(f.x), "=f"(f.y) : "l"(a)); return f;
}

// ---- tf32 / mma helpers ----
__device__ __forceinline__ uint32_t f2tf(float x){
    uint32_t r; asm("cvt.rna.tf32.f32 %0, %1;" : "=r"(r) : "f"(x)); return r;
}
__device__ __forceinline__ void mma_tf32(float (&c)[4], const uint32_t (&a)[4], const uint32_t (&b)[2]){
    asm volatile("mma.sync.aligned.m16n8k8.row.col.f32.tf32.tf32.f32 "
        "{%0,%1,%2,%3}, {%4,%5,%6,%7}, {%8,%9}, {%0,%1,%2,%3};"
        : "+f"(c[0]), "+f"(c[1]), "+f"(c[2]), "+f"(c[3])
        : "r"(a[0]), "r"(a[1]), "r"(a[2]), "r"(a[3]), "r"(b[0]), "r"(b[1]));
}
__device__ __forceinline__ float ex2(float x){
    float r; asm("ex2.approx.f32 %0, %1;" : "=f"(r) : "f"(x)); return r;
}

// ---------------------------------------------------------------------------
// SIMT fp32 GEMM (proven): C[m,n] = sum_k A[m,k]*W[n,k] + bias[n]
// ---------------------------------------------------------------------------
__device__ __forceinline__ void gemm_body(
    const float* __restrict__ A, const float* __restrict__ W,
    const float* __restrict__ bias, float* __restrict__ C,
    int m0, int n0)
{
    __shared__ __align__(16) float As[16][68];
    __shared__ __align__(16) float Bs[16][68];

    const int tid = threadIdx.x;
    const int lr = tid >> 2;
    const int lv = tid & 3;
    const int tx = tid & 15;
    const int ty = tid >> 4;

    u64 c2[4][2];
    #pragma unroll
    for (int r = 0; r < 4; r++) { c2[r][0] = 0ull; c2[r][1] = 0ull; }

    for (int k0 = 0; k0 < DD; k0 += 16) {
        float4 av = *(const float4*)&A[(m0 + lr) * DD + k0 + lv * 4];
        float4 bv = *(const float4*)&W[(n0 + lr) * DD + k0 + lv * 4];
        __syncthreads();
        As[lv*4+0][lr] = av.x; As[lv*4+1][lr] = av.y;
        As[lv*4+2][lr] = av.z; As[lv*4+3][lr] = av.w;
        Bs[lv*4+0][lr] = bv.x; Bs[lv*4+1][lr] = bv.y;
        Bs[lv*4+2][lr] = bv.z; Bs[lv*4+3][lr] = bv.w;
        __syncthreads();
        #pragma unroll
        for (int kk = 0; kk < 16; kk++) {
            float4 a4 = *(const float4*)&As[kk][ty * 4];
            ulonglong2 bp = *(const ulonglong2*)&Bs[kk][tx * 4];
            u64 a0 = pack2(a4.x, a4.x);
            u64 a1 = pack2(a4.y, a4.y);
            u64 a2 = pack2(a4.z, a4.z);
            u64 a3 = pack2(a4.w, a4.w);
            c2[0][0] = ffma2(a0, bp.x, c2[0][0]); c2[0][1] = ffma2(a0, bp.y, c2[0][1]);
            c2[1][0] = ffma2(a1, bp.x, c2[1][0]); c2[1][1] = ffma2(a1, bp.y, c2[1][1]);
            c2[2][0] = ffma2(a2, bp.x, c2[2][0]); c2[2][1] = ffma2(a2, bp.y, c2[2][1]);
            c2[3][0] = ffma2(a3, bp.x, c2[3][0]); c2[3][1] = ffma2(a3, bp.y, c2[3][1]);
        }
    }

    const int n = n0 + tx * 4;
    float4 bb = *(const float4*)&bias[n];
    #pragma unroll
    for (int r = 0; r < 4; r++) {
        float2 lo = unpack2(c2[r][0]);
        float2 hi = unpack2(c2[r][1]);
        float4 o;
        o.x = lo.x + bb.x; o.y = lo.y + bb.y;
        o.z = hi.x + bb.z; o.w = hi.y + bb.w;
        *(float4*)&C[(m0 + ty*4 + r) * DD + n] = o;
    }
}

struct QKVArgs {
    const float *Wq, *bq, *Wk, *bk, *Wv, *bv;
    float *q, *k, *v;
};

__global__ __launch_bounds__(256) void gemm_qkv(const float* __restrict__ x, QKVArgs a)
{
    const float* W; const float* b; float* C;
    if (blockIdx.z == 0)      { W = a.Wq; b = a.bq; C = a.q; }
    else if (blockIdx.z == 1) { W = a.Wk; b = a.bk; C = a.k; }
    else                      { W = a.Wv; b = a.bv; C = a.v; }
    gemm_body(x, W, b, C, blockIdx.y * 64, blockIdx.x * 64);
}

__global__ __launch_bounds__(256) void gemm_single(
    const float* __restrict__ A, const float* __restrict__ W,
    const float* __restrict__ bias, float* __restrict__ C)
{
    gemm_body(A, W, bias, C, blockIdx.y * 64, blockIdx.x * 64);
}

// ---------------------------------------------------------------------------
// Wcomb = Wfc @ Wo, bcomb = Wfc @ bo + bfc  (fuses the two output GEMMs)
// ---------------------------------------------------------------------------
__global__ __launch_bounds__(256) void wcomb_kernel(
    const float* __restrict__ Wfc, const float* __restrict__ Wo,
    float* __restrict__ Wc)
{
    __shared__ float wf[DD];
    const int n = blockIdx.x;
    const int kx = threadIdx.x;
    wf[kx] = Wfc[n * DD + kx];
    __syncthreads();
    float a0 = 0.f, a1 = 0.f, a2 = 0.f, a3 = 0.f;
    #pragma unroll 4
    for (int j = 0; j < DD; j += 4) {
        a0 = fmaf(wf[j+0], Wo[(j+0) * DD + kx], a0);
        a1 = fmaf(wf[j+1], Wo[(j+1) * DD + kx], a1);
        a2 = fmaf(wf[j+2], Wo[(j+2) * DD + kx], a2);
        a3 = fmaf(wf[j+3], Wo[(j+3) * DD + kx], a3);
    }
    Wc[n * DD + kx] = (a0 + a1) + (a2 + a3);
}

__global__ __launch_bounds__(256) void bcomb_kernel(
    const float* __restrict__ Wfc, const float* __restrict__ bo,
    const float* __restrict__ bfc, float* __restrict__ bc)
{
    const int n = threadIdx.x;
    float acc = bfc[n];
    for (int j = 0; j < DD; j++) acc = fmaf(Wfc[n * DD + j], bo[j], acc);
    bc[n] = acc;
}

// ---------------------------------------------------------------------------
// expmap0 for q and k (blockIdx.y selects tensor). Writes {tanh^2, cosh^2}.
// ---------------------------------------------------------------------------
__global__ __launch_bounds__(256) void expmap_kernel(
    float* __restrict__ q, float* __restrict__ k, float2* __restrict__ sq)
{
    float* p   = blockIdx.y ? k : q;
    float2* so = sq + blockIdx.y * (NROWS*HH);
    const int row  = blockIdx.x;
    const int h    = threadIdx.x >> 5;
    const int lane = threadIdx.x & 31;
    const int idx  = row * DD + h * DH + lane;
    float v = p[idx];
    float s = v * v;
    #pragma unroll
    for (int o = 16; o; o >>= 1) s += __shfl_xor_sync(0xffffffffu, s, o);
    float n2  = fmaxf(s, 1e-12f);
    float nrm = sqrtf(n2);
    float t   = tanhf(nrm);
    p[idx] = v * (t / nrm);
    if (lane == 0) {
        float ch = coshf(nrm);
        so[row * HH + h] = make_float2(t * t, ch * ch);
    }
}

// ---------------------------------------------------------------------------
// Attention via mma.sync tf32.
//   cosh(dist) = u = 1 + (qq + kk - 2 qk) * (2 * ch2_q * ch2_k)
//   g = u + sqrt(u^2-1) = e^dist, clip: u >= UCLIP -> w = WCLIP (continuous).
//   w = g^(-1/sqrt(32)). Scores in [-2.158, 0] => plain sum softmax.
// Block = 4 warps x 32 q rows; keys tiled 64 (two 32-halves).
// S: 1-pass tf32 (clip margin dwarfs tf32 error); PV: 1-pass tf32 (P
// quantization is common-mode in softmax; V quantization ~2^-11 << 1e-3 gate).
// sK padded to 36 (conflict-free S-phase column reads: banks 4g+t4);
// sV padded to 40 (conflict-free PV B-frag reads: banks 8t4+g).
// ---------------------------------------------------------------------------
#define KT 64
#define SC_EXP 0.17677669529663689f   /* 1/sqrt(32) */
#define UCLIP  99999.5f               /* cosh(dist_max), dist_max=2 atanh(1-1e-5) */
#define WCLIP  0.11558618f            /* exp(-dist_max/sqrt(32)) */

__global__ __launch_bounds__(128) void attn_kernel(
    const float* __restrict__ q, const float* __restrict__ k,
    const float* __restrict__ v, const float2* __restrict__ sq2,
    float* __restrict__ ctx)
{
    __shared__ __align__(16) float sK[KT][36];
    __shared__ __align__(16) float sV[KT][40];
    __shared__ __align__(8)  float sP[128][34];
    __shared__ float2 sKC[KT];

    const int b   = blockIdx.z;
    const int h   = blockIdx.y;
    const int q0  = blockIdx.x * 128;
    const int tid = threadIdx.x;
    const int w   = tid >> 5;
    const int lane= tid & 31;
    const int g   = lane >> 2;
    const int t4  = lane & 3;
    const int wrow = w * 32;

    const float2* cq = sq2;               // q-side {tanh^2, cosh^2}
    const float2* ck = sq2 + NROWS*HH;    // k-side

    // per-thread row constants (rows wrow + m*16 + rh*8 + g)
    float qqr[4], fr2[4];
    #pragma unroll
    for (int m = 0; m < 2; m++)
        #pragma unroll
        for (int rh = 0; rh < 2; rh++) {
            int r = b*SS + q0 + wrow + m*16 + rh*8 + g;
            float2 c = cq[r*HH + h];
            qqr[m*2+rh] = c.x;
            fr2[m*2+rh] = 2.0f * c.y;
        }

    // Q fragments (1-pass tf32), persistent across all key tiles
    uint32_t qh[2][4][4];
    #pragma unroll
    for (int m = 0; m < 2; m++)
        #pragma unroll
        for (int ks = 0; ks < 4; ks++) {
            int r0 = b*SS + q0 + wrow + m*16 + g;
            int c0 = h*DH + ks*8 + t4;
            qh[m][ks][0] = f2tf(q[r0*DD + c0]);
            qh[m][ks][1] = f2tf(q[(r0+8)*DD + c0]);
            qh[m][ks][2] = f2tf(q[r0*DD + c0 + 4]);
            qh[m][ks][3] = f2tf(q[(r0+8)*DD + c0 + 4]);
        }

    float O[2][4][4];
    #pragma unroll
    for (int m = 0; m < 2; m++)
        #pragma unroll
        for (int nt = 0; nt < 4; nt++)
            #pragma unroll
            for (int r = 0; r < 4; r++) O[m][nt][r] = 0.0f;
    float lacc[4] = {0.f, 0.f, 0.f, 0.f};

    #pragma unroll 1
    for (int t0 = 0; t0 < SS; t0 += KT) {
        __syncthreads();
        #pragma unroll
        for (int i = 0; i < 4; i++) {
            int l = tid + i*128;          // 0..511
            int row = l >> 3, j = l & 7;
            *(float4*)&sK[row][j*4] = *(const float4*)&k[(b*SS+t0+row)*DD + h*DH + j*4];
            *(float4*)&sV[row][j*4] = *(const float4*)&v[(b*SS+t0+row)*DD + h*DH + j*4];
        }
        if (tid < KT) sKC[tid] = ck[(b*SS + t0 + tid)*HH + h];
        __syncthreads();

        #pragma unroll 1
        for (int half = 0; half < 2; half++) {
            // ---- S = Q K^T for keys [half*32, half*32+32) ----
            float S[2][4][4];
            #pragma unroll
            for (int m = 0; m < 2; m++)
                #pragma unroll
                for (int nt = 0; nt < 4; nt++)
                    #pragma unroll
                    for (int r = 0; r < 4; r++) S[m][nt][r] = 0.0f;

            #pragma unroll
            for (int nt = 0; nt < 4; nt++) {
                int kr = half*32 + nt*8 + g;
                #pragma unroll
                for (int ks = 0; ks < 4; ks++) {
                    uint32_t bh[2];
                    bh[0] = f2tf(sK[kr][ks*8 + t4]);
                    bh[1] = f2tf(sK[kr][ks*8 + t4 + 4]);
                    mma_tf32(S[0][nt], qh[0][ks], bh);
                    mma_tf32(S[1][nt], qh[1][ks], bh);
                }
            }

            // ---- qk -> softmax weight (clip fast path: no MUFU) ----
            #pragma unroll
            for (int m = 0; m < 2; m++)
                #pragma unroll
                for (int nt = 0; nt < 4; nt++)
                    #pragma unroll
                    for (int r = 0; r < 4; r++) {
                        int col  = half*32 + nt*8 + 2*t4 + (r & 1);
                        int ridx = m*2 + (r >> 1);
                        float2 kc = sKC[col];
                        float nm = fmaf(-2.0f, S[m][nt][r], qqr[ridx] + kc.x);
                        float u  = fmaf(nm, fr2[ridx] * kc.y, 1.0f);
                        float w_ = WCLIP;
                        if (u < UCLIP) {
                            float t = fmaf(u, u, -1.0f);
                            t = fmaxf(t, 0.0f);
                            float gg = u + t * rsqrtf(fmaxf(t, 1e-30f));
                            gg = fmaxf(gg, 1.0f);
                            w_ = ex2(-SC_EXP * __log2f(gg));
                        }
                        lacc[ridx] += w_;
                        S[m][nt][r] = w_;
                    }

            // ---- P roundtrip through smem (own warp's rows only) ----
            #pragma unroll
            for (int m = 0; m < 2; m++)
                #pragma unroll
                for (int nt = 0; nt < 4; nt++) {
                    int pr = wrow + m*16 + g;
                    *(float2*)&sP[pr][nt*8 + 2*t4]   = make_float2(S[m][nt][0], S[m][nt][1]);
                    *(float2*)&sP[pr+8][nt*8 + 2*t4] = make_float2(S[m][nt][2], S[m][nt][3]);
                }
            __syncwarp();

            // ---- O += P V  (both 1-pass tf32) ----
            #pragma unroll
            for (int ks = 0; ks < 4; ks++) {
                uint32_t ah[2][4];
                #pragma unroll
                for (int m = 0; m < 2; m++) {
                    int pr = wrow + m*16 + g;
                    ah[m][0] = f2tf(sP[pr][ks*8 + t4]);
                    ah[m][1] = f2tf(sP[pr+8][ks*8 + t4]);
                    ah[m][2] = f2tf(sP[pr][ks*8 + t4 + 4]);
                    ah[m][3] = f2tf(sP[pr+8][ks*8 + t4 + 4]);
                }
                int kb = half*32 + ks*8;
                #pragma unroll
                for (int nt = 0; nt < 4; nt++) {
                    uint32_t bh[2];
                    bh[0] = f2tf(sV[kb + t4][nt*8 + g]);
                    bh[1] = f2tf(sV[kb + t4 + 4][nt*8 + g]);
                    mma_tf32(O[0][nt], ah[0], bh);
                    mma_tf32(O[1][nt], ah[1], bh);
                }
            }
            __syncwarp();
        }
    }

    // ---- epilogue: reduce l over quad, normalize, store ----
    #pragma unroll
    for (int i = 0; i < 4; i++) {
        lacc[i] += __shfl_xor_sync(0xffffffffu, lacc[i], 1);
        lacc[i] += __shfl_xor_sync(0xffffffffu, lacc[i], 2);
        lacc[i] = __fdividef(1.0f, lacc[i]);
    }
    #pragma unroll
    for (int m = 0; m < 2; m++)
        #pragma unroll
        for (int rh = 0; rh < 2; rh++) {
            int grow = b*SS + q0 + wrow + m*16 + rh*8 + g;
            float rl = lacc[m*2 + rh];
            #pragma unroll
            for (int nt = 0; nt < 4; nt++) {
                float2 o;
                o.x = O[m][nt][rh*2 + 0] * rl;
                o.y = O[m][nt][rh*2 + 1] * rl;
                *(float2*)&ctx[grow*DD + h*DH + nt*8 + 2*t4] = o;
            }
        }
}

// ---------------------------------------------------------------------------

extern "C" void kernel_launch(void* const* d_in, const int* in_sizes, int n_in,
                              void* d_out, int out_size)
{
    const float* x   = (const float*)d_in[0];
    const float* Wq  = (const float*)d_in[1];
    const float* bq  = (const float*)d_in[2];
    const float* Wk  = (const float*)d_in[3];
    const float* bk  = (const float*)d_in[4];
    const float* Wv  = (const float*)d_in[5];
    const float* bv  = (const float*)d_in[6];
    const float* Wo  = (const float*)d_in[7];
    const float* bo  = (const float*)d_in[8];
    const float* Wfc = (const float*)d_in[9];
    const float* bfc = (const float*)d_in[10];
    float* out = (float*)d_out;

    float *q, *k, *v, *ctx, *wc, *bc;
    float2* sq;
    cudaGetSymbolAddress((void**)&q,   g_q);
    cudaGetSymbolAddress((void**)&k,   g_k);
    cudaGetSymbolAddress((void**)&v,   g_v);
    cudaGetSymbolAddress((void**)&ctx, g_ctx);
    cudaGetSymbolAddress((void**)&sq,  g_sq);
    cudaGetSymbolAddress((void**)&wc,  g_wc);
    cudaGetSymbolAddress((void**)&bc,  g_bc);

    // Combined output weights (fuses Wo and Wfc GEMMs)
    wcomb_kernel<<<DD, DD>>>(Wfc, Wo, wc);
    bcomb_kernel<<<1, DD>>>(Wfc, bo, bfc, bc);

    // Q/K/V projections in one launch
    QKVArgs a { Wq, bq, Wk, bk, Wv, bv, q, k, v };
    dim3 qkvgrid(DD / 64, NROWS / 64, 3);
    gemm_qkv<<<qkvgrid, 256>>>(x, a);

    // expmap0 on q and k
    dim3 egrid(NROWS, 2);
    expmap_kernel<<<egrid, 256>>>(q, k, sq);

    // attention (tf32 mma)
    dim3 agrid(SS / 128, HH, BB);
    attn_kernel<<<agrid, 128>>>(q, k, v, sq, ctx);

    // fused output projection + fc
    dim3 ggrid(DD / 64, NROWS / 64);
    gemm_single<<<ggrid, 256>>>(ctx, wc, bc, out);
}

// round 8
// speedup vs baseline: 2.2519x; 1.2111x over previous
#include <cuda_runtime.h>
#include <cstdint>

#define BB 2
#define SS 2048
#define DD 256
#define HH 8
#define DH 32
#define NROWS (BB*SS)   // 4096

// Scratch (device globals: no allocation allowed)
__device__ float g_q[NROWS*DD];
__device__ float g_k[NROWS*DD];
__device__ float g_v[NROWS*DD];
__device__ float g_ctx[NROWS*DD];
__device__ float2 g_sq[2*NROWS*HH];  // {tanh^2, cosh^2}: [0..)=q rows, [NROWS*HH..)=k rows
__device__ float g_wc[DD*DD];
__device__ float g_bc[DD];

typedef unsigned long long u64;

// ---- Blackwell packed f32x2 helpers ----
__device__ __forceinline__ u64 ffma2(u64 a, u64 b, u64 c){
    u64 d; asm("fma.rn.f32x2 %0, %1, %2, %3;" : "=l"(d) : "l"(a), "l"(b), "l"(c)); return d;
}
__device__ __forceinline__ u64 pack2(float x, float y){
    u64 r; asm("mov.b64 %0, {%1, %2};" : "=l"(r) : "f"(x), "f"(y)); return r;
}
__device__ __forceinline__ float2 unpack2(u64 a){
    float2 f; asm("mov.b64 {%0, %1}, %2;" : "=f"(f.x), "=f"(f.y) : "l"(a)); return f;
}

// ---- tf32 / f16 mma helpers ----
__device__ __forceinline__ uint32_t f2tf(float x){
    uint32_t r; asm("cvt.rna.tf32.f32 %0, %1;" : "=r"(r) : "f"(x)); return r;
}
__device__ __forceinline__ uint32_t h2(float lo, float hi){
    uint32_t r; asm("cvt.rn.f16x2.f32 %0, %1, %2;" : "=r"(r) : "f"(hi), "f"(lo)); return r;
}
__device__ __forceinline__ void mma_tf32(float (&c)[4], const uint32_t (&a)[4], const uint32_t (&b)[2]){
    asm volatile("mma.sync.aligned.m16n8k8.row.col.f32.tf32.tf32.f32 "
        "{%0,%1,%2,%3}, {%4,%5,%6,%7}, {%8,%9}, {%0,%1,%2,%3};"
        : "+f"(c[0]), "+f"(c[1]), "+f"(c[2]), "+f"(c[3])
        : "r"(a[0]), "r"(a[1]), "r"(a[2]), "r"(a[3]), "r"(b[0]), "r"(b[1]));
}
__device__ __forceinline__ void mma_f16(float (&c)[4], const uint32_t (&a)[4], const uint32_t (&b)[2]){
    asm volatile("mma.sync.aligned.m16n8k16.row.col.f32.f16.f16.f32 "
        "{%0,%1,%2,%3}, {%4,%5,%6,%7}, {%8,%9}, {%0,%1,%2,%3};"
        : "+f"(c[0]), "+f"(c[1]), "+f"(c[2]), "+f"(c[3])
        : "r"(a[0]), "r"(a[1]), "r"(a[2]), "r"(a[3]), "r"(b[0]), "r"(b[1]));
}
__device__ __forceinline__ float ex2(float x){
    float r; asm("ex2.approx.f32 %0, %1;" : "=f"(r) : "f"(x)); return r;
}

// ---------------------------------------------------------------------------
// SIMT fp32 GEMM (proven): C[m,n] = sum_k A[m,k]*W[n,k] + bias[n]
// ---------------------------------------------------------------------------
__device__ __forceinline__ void gemm_body(
    const float* __restrict__ A, const float* __restrict__ W,
    const float* __restrict__ bias, float* __restrict__ C,
    int m0, int n0)
{
    __shared__ __align__(16) float As[16][68];
    __shared__ __align__(16) float Bs[16][68];

    const int tid = threadIdx.x;
    const int lr = tid >> 2;
    const int lv = tid & 3;
    const int tx = tid & 15;
    const int ty = tid >> 4;

    u64 c2[4][2];
    #pragma unroll
    for (int r = 0; r < 4; r++) { c2[r][0] = 0ull; c2[r][1] = 0ull; }

    for (int k0 = 0; k0 < DD; k0 += 16) {
        float4 av = *(const float4*)&A[(m0 + lr) * DD + k0 + lv * 4];
        float4 bv = *(const float4*)&W[(n0 + lr) * DD + k0 + lv * 4];
        __syncthreads();
        As[lv*4+0][lr] = av.x; As[lv*4+1][lr] = av.y;
        As[lv*4+2][lr] = av.z; As[lv*4+3][lr] = av.w;
        Bs[lv*4+0][lr] = bv.x; Bs[lv*4+1][lr] = bv.y;
        Bs[lv*4+2][lr] = bv.z; Bs[lv*4+3][lr] = bv.w;
        __syncthreads();
        #pragma unroll
        for (int kk = 0; kk < 16; kk++) {
            float4 a4 = *(const float4*)&As[kk][ty * 4];
            ulonglong2 bp = *(const ulonglong2*)&Bs[kk][tx * 4];
            u64 a0 = pack2(a4.x, a4.x);
            u64 a1 = pack2(a4.y, a4.y);
            u64 a2 = pack2(a4.z, a4.z);
            u64 a3 = pack2(a4.w, a4.w);
            c2[0][0] = ffma2(a0, bp.x, c2[0][0]); c2[0][1] = ffma2(a0, bp.y, c2[0][1]);
            c2[1][0] = ffma2(a1, bp.x, c2[1][0]); c2[1][1] = ffma2(a1, bp.y, c2[1][1]);
            c2[2][0] = ffma2(a2, bp.x, c2[2][0]); c2[2][1] = ffma2(a2, bp.y, c2[2][1]);
            c2[3][0] = ffma2(a3, bp.x, c2[3][0]); c2[3][1] = ffma2(a3, bp.y, c2[3][1]);
        }
    }

    const int n = n0 + tx * 4;
    float4 bb = *(const float4*)&bias[n];
    #pragma unroll
    for (int r = 0; r < 4; r++) {
        float2 lo = unpack2(c2[r][0]);
        float2 hi = unpack2(c2[r][1]);
        float4 o;
        o.x = lo.x + bb.x; o.y = lo.y + bb.y;
        o.z = hi.x + bb.z; o.w = hi.y + bb.w;
        *(float4*)&C[(m0 + ty*4 + r) * DD + n] = o;
    }
}

struct QKVArgs {
    const float *Wq, *bq, *Wk, *bk, *Wv, *bv;
    float *q, *k, *v;
};

__global__ __launch_bounds__(256) void gemm_qkv(const float* __restrict__ x, QKVArgs a)
{
    const float* W; const float* b; float* C;
    if (blockIdx.z == 0)      { W = a.Wq; b = a.bq; C = a.q; }
    else if (blockIdx.z == 1) { W = a.Wk; b = a.bk; C = a.k; }
    else                      { W = a.Wv; b = a.bv; C = a.v; }
    gemm_body(x, W, b, C, blockIdx.y * 64, blockIdx.x * 64);
}

__global__ __launch_bounds__(256) void gemm_single(
    const float* __restrict__ A, const float* __restrict__ W,
    const float* __restrict__ bias, float* __restrict__ C)
{
    gemm_body(A, W, bias, C, blockIdx.y * 64, blockIdx.x * 64);
}

// ---------------------------------------------------------------------------
// Wcomb = Wfc @ Wo, bcomb = Wfc @ bo + bfc  (fuses the two output GEMMs)
// ---------------------------------------------------------------------------
__global__ __launch_bounds__(256) void wcomb_kernel(
    const float* __restrict__ Wfc, const float* __restrict__ Wo,
    float* __restrict__ Wc)
{
    __shared__ float wf[DD];
    const int n = blockIdx.x;
    const int kx = threadIdx.x;
    wf[kx] = Wfc[n * DD + kx];
    __syncthreads();
    float a0 = 0.f, a1 = 0.f, a2 = 0.f, a3 = 0.f;
    #pragma unroll 4
    for (int j = 0; j < DD; j += 4) {
        a0 = fmaf(wf[j+0], Wo[(j+0) * DD + kx], a0);
        a1 = fmaf(wf[j+1], Wo[(j+1) * DD + kx], a1);
        a2 = fmaf(wf[j+2], Wo[(j+2) * DD + kx], a2);
        a3 = fmaf(wf[j+3], Wo[(j+3) * DD + kx], a3);
    }
    Wc[n * DD + kx] = (a0 + a1) + (a2 + a3);
}

__global__ __launch_bounds__(256) void bcomb_kernel(
    const float* __restrict__ Wfc, const float* __restrict__ bo,
    const float* __restrict__ bfc, float* __restrict__ bc)
{
    const int n = threadIdx.x;
    float acc = bfc[n];
    for (int j = 0; j < DD; j++) acc = fmaf(Wfc[n * DD + j], bo[j], acc);
    bc[n] = acc;
}

// ---------------------------------------------------------------------------
// expmap0 for q and k (blockIdx.y selects tensor). Writes {tanh^2, cosh^2}.
// ---------------------------------------------------------------------------
__global__ __launch_bounds__(256) void expmap_kernel(
    float* __restrict__ q, float* __restrict__ k, float2* __restrict__ sq)
{
    float* p   = blockIdx.y ? k : q;
    float2* so = sq + blockIdx.y * (NROWS*HH);
    const int row  = blockIdx.x;
    const int h    = threadIdx.x >> 5;
    const int lane = threadIdx.x & 31;
    const int idx  = row * DD + h * DH + lane;
    float v = p[idx];
    float s = v * v;
    #pragma unroll
    for (int o = 16; o; o >>= 1) s += __shfl_xor_sync(0xffffffffu, s, o);
    float n2  = fmaxf(s, 1e-12f);
    float nrm = sqrtf(n2);
    float t   = tanhf(nrm);
    p[idx] = v * (t / nrm);
    if (lane == 0) {
        float ch = coshf(nrm);
        so[row * HH + h] = make_float2(t * t, ch * ch);
    }
}

// ---------------------------------------------------------------------------
// Attention: tf32 mma for S = QK^T, fp16 mma (m16n8k16) for O += P V.
//   cosh(dist) = u = 1 + (qq + kk - 2 qk) * (2 * ch2_q * ch2_k)
//   g = u + sqrt(u^2-1) = e^dist; clip u >= UCLIP -> w = WCLIP (continuous).
//   w = g^(-1/sqrt(32)). Scores in [-2.158, 0] => plain sum softmax.
// fp16 PV: the f16 m16n8k16 A-fragment layout (packed col pairs 2t4,2t4+1)
// matches the S C-fragment exactly, so P feeds the next mma straight from
// registers via cvt.rn.f16x2 -- no smem roundtrip, no shuffles.
// V read from fp32 smem as row pairs (stride 36 => bank 8*t4+g, conflict-free)
// and packed to f16x2. w in [0.1156,1] and |V|~1: fp16 adds ~2.4e-4 rms.
// ---------------------------------------------------------------------------
#define KT 64
#define SC_EXP 0.17677669529663689f   /* 1/sqrt(32) */
#define UCLIP  99999.5f               /* cosh(dist_max), dist_max=2 atanh(1-1e-5) */
#define WCLIP  0.11558618f            /* exp(-dist_max/sqrt(32)) */

__global__ __launch_bounds__(128) void attn_kernel(
    const float* __restrict__ q, const float* __restrict__ k,
    const float* __restrict__ v, const float2* __restrict__ sq2,
    float* __restrict__ ctx)
{
    __shared__ __align__(16) float sK[KT][36];
    __shared__ __align__(16) float sV[KT][36];
    __shared__ float2 sKC[KT];

    const int b   = blockIdx.z;
    const int h   = blockIdx.y;
    const int q0  = blockIdx.x * 128;
    const int tid = threadIdx.x;
    const int w   = tid >> 5;
    const int lane= tid & 31;
    const int g   = lane >> 2;
    const int t4  = lane & 3;
    const int wrow = w * 32;

    const float2* cq = sq2;               // q-side {tanh^2, cosh^2}
    const float2* ck = sq2 + NROWS*HH;    // k-side

    // per-thread row constants (rows wrow + m*16 + rh*8 + g)
    float qqr[4], fr2[4];
    #pragma unroll
    for (int m = 0; m < 2; m++)
        #pragma unroll
        for (int rh = 0; rh < 2; rh++) {
            int r = b*SS + q0 + wrow + m*16 + rh*8 + g;
            float2 c = cq[r*HH + h];
            qqr[m*2+rh] = c.x;
            fr2[m*2+rh] = 2.0f * c.y;
        }

    // Q fragments (1-pass tf32), persistent across all key tiles
    uint32_t qh[2][4][4];
    #pragma unroll
    for (int m = 0; m < 2; m++)
        #pragma unroll
        for (int ks = 0; ks < 4; ks++) {
            int r0 = b*SS + q0 + wrow + m*16 + g;
            int c0 = h*DH + ks*8 + t4;
            qh[m][ks][0] = f2tf(q[r0*DD + c0]);
            qh[m][ks][1] = f2tf(q[(r0+8)*DD + c0]);
            qh[m][ks][2] = f2tf(q[r0*DD + c0 + 4]);
            qh[m][ks][3] = f2tf(q[(r0+8)*DD + c0 + 4]);
        }

    float O[2][4][4];
    #pragma unroll
    for (int m = 0; m < 2; m++)
        #pragma unroll
        for (int nt = 0; nt < 4; nt++)
            #pragma unroll
            for (int r = 0; r < 4; r++) O[m][nt][r] = 0.0f;
    float lacc[4] = {0.f, 0.f, 0.f, 0.f};

    #pragma unroll 1
    for (int t0 = 0; t0 < SS; t0 += KT) {
        __syncthreads();
        #pragma unroll
        for (int i = 0; i < 4; i++) {
            int l = tid + i*128;          // 0..511
            int row = l >> 3, j = l & 7;
            *(float4*)&sK[row][j*4] = *(const float4*)&k[(b*SS+t0+row)*DD + h*DH + j*4];
            *(float4*)&sV[row][j*4] = *(const float4*)&v[(b*SS+t0+row)*DD + h*DH + j*4];
        }
        if (tid < KT) sKC[tid] = ck[(b*SS + t0 + tid)*HH + h];
        __syncthreads();

        #pragma unroll 1
        for (int half = 0; half < 2; half++) {
            // ---- S = Q K^T for keys [half*32, half*32+32) ----
            float S[2][4][4];
            #pragma unroll
            for (int m = 0; m < 2; m++)
                #pragma unroll
                for (int nt = 0; nt < 4; nt++)
                    #pragma unroll
                    for (int r = 0; r < 4; r++) S[m][nt][r] = 0.0f;

            #pragma unroll
            for (int nt = 0; nt < 4; nt++) {
                int kr = half*32 + nt*8 + g;
                #pragma unroll
                for (int ks = 0; ks < 4; ks++) {
                    uint32_t bh[2];
                    bh[0] = f2tf(sK[kr][ks*8 + t4]);
                    bh[1] = f2tf(sK[kr][ks*8 + t4 + 4]);
                    mma_tf32(S[0][nt], qh[0][ks], bh);
                    mma_tf32(S[1][nt], qh[1][ks], bh);
                }
            }

            // ---- qk -> softmax weight (clip fast path: no MUFU) ----
            #pragma unroll
            for (int m = 0; m < 2; m++)
                #pragma unroll
                for (int nt = 0; nt < 4; nt++)
                    #pragma unroll
                    for (int r = 0; r < 4; r++) {
                        int col  = half*32 + nt*8 + 2*t4 + (r & 1);
                        int ridx = m*2 + (r >> 1);
                        float2 kc = sKC[col];
                        float nm = fmaf(-2.0f, S[m][nt][r], qqr[ridx] + kc.x);
                        float u  = fmaf(nm, fr2[ridx] * kc.y, 1.0f);
                        float w_ = WCLIP;
                        if (u < UCLIP) {
                            float t = fmaf(u, u, -1.0f);
                            t = fmaxf(t, 0.0f);
                            float gg = u + t * rsqrtf(fmaxf(t, 1e-30f));
                            gg = fmaxf(gg, 1.0f);
                            w_ = ex2(-SC_EXP * __log2f(gg));
                        }
                        lacc[ridx] += w_;
                        S[m][nt][r] = w_;
                    }

            // ---- pack P into f16 A-fragments (register-only, layout match) ----
            uint32_t pa[2][2][4];   // [m][kchunk][frag]
            #pragma unroll
            for (int m = 0; m < 2; m++)
                #pragma unroll
                for (int kc2 = 0; kc2 < 2; kc2++) {
                    int nt0 = 2*kc2, nt1 = 2*kc2 + 1;
                    pa[m][kc2][0] = h2(S[m][nt0][0], S[m][nt0][1]);
                    pa[m][kc2][1] = h2(S[m][nt0][2], S[m][nt0][3]);
                    pa[m][kc2][2] = h2(S[m][nt1][0], S[m][nt1][1]);
                    pa[m][kc2][3] = h2(S[m][nt1][2], S[m][nt1][3]);
                }

            // ---- O += P V  (fp16 m16n8k16; V packed from fp32 smem) ----
            #pragma unroll
            for (int kc2 = 0; kc2 < 2; kc2++) {
                int kb = half*32 + kc2*16;
                #pragma unroll
                for (int nt = 0; nt < 4; nt++) {
                    int col = nt*8 + g;
                    uint32_t bb[2];
                    bb[0] = h2(sV[kb + 2*t4][col],     sV[kb + 2*t4 + 1][col]);
                    bb[1] = h2(sV[kb + 8 + 2*t4][col], sV[kb + 9 + 2*t4][col]);
                    mma_f16(O[0][nt], pa[0][kc2], bb);
                    mma_f16(O[1][nt], pa[1][kc2], bb);
                }
            }
        }
    }

    // ---- epilogue: reduce l over quad, normalize, store ----
    #pragma unroll
    for (int i = 0; i < 4; i++) {
        lacc[i] += __shfl_xor_sync(0xffffffffu, lacc[i], 1);
        lacc[i] += __shfl_xor_sync(0xffffffffu, lacc[i], 2);
        lacc[i] = __fdividef(1.0f, lacc[i]);
    }
    #pragma unroll
    for (int m = 0; m < 2; m++)
        #pragma unroll
        for (int rh = 0; rh < 2; rh++) {
            int grow = b*SS + q0 + wrow + m*16 + rh*8 + g;
            float rl = lacc[m*2 + rh];
            #pragma unroll
            for (int nt = 0; nt < 4; nt++) {
                float2 o;
                o.x = O[m][nt][rh*2 + 0] * rl;
                o.y = O[m][nt][rh*2 + 1] * rl;
                *(float2*)&ctx[grow*DD + h*DH + nt*8 + 2*t4] = o;
            }
        }
}

// ---------------------------------------------------------------------------

extern "C" void kernel_launch(void* const* d_in, const int* in_sizes, int n_in,
                              void* d_out, int out_size)
{
    const float* x   = (const float*)d_in[0];
    const float* Wq  = (const float*)d_in[1];
    const float* bq  = (const float*)d_in[2];
    const float* Wk  = (const float*)d_in[3];
    const float* bk  = (const float*)d_in[4];
    const float* Wv  = (const float*)d_in[5];
    const float* bv  = (const float*)d_in[6];
    const float* Wo  = (const float*)d_in[7];
    const float* bo  = (const float*)d_in[8];
    const float* Wfc = (const float*)d_in[9];
    const float* bfc = (const float*)d_in[10];
    float* out = (float*)d_out;

    float *q, *k, *v, *ctx, *wc, *bc;
    float2* sq;
    cudaGetSymbolAddress((void**)&q,   g_q);
    cudaGetSymbolAddress((void**)&k,   g_k);
    cudaGetSymbolAddress((void**)&v,   g_v);
    cudaGetSymbolAddress((void**)&ctx, g_ctx);
    cudaGetSymbolAddress((void**)&sq,  g_sq);
    cudaGetSymbolAddress((void**)&wc,  g_wc);
    cudaGetSymbolAddress((void**)&bc,  g_bc);

    // Combined output weights (fuses Wo and Wfc GEMMs)
    wcomb_kernel<<<DD, DD>>>(Wfc, Wo, wc);
    bcomb_kernel<<<1, DD>>>(Wfc, bo, bfc, bc);

    // Q/K/V projections in one launch
    QKVArgs a { Wq, bq, Wk, bk, Wv, bv, q, k, v };
    dim3 qkvgrid(DD / 64, NROWS / 64, 3);
    gemm_qkv<<<qkvgrid, 256>>>(x, a);

    // expmap0 on q and k
    dim3 egrid(NROWS, 2);
    expmap_kernel<<<egrid, 256>>>(q, k, sq);

    // attention (tf32 S, fp16 PV)
    dim3 agrid(SS / 128, HH, BB);
    attn_kernel<<<agrid, 128>>>(q, k, v, sq, ctx);

    // fused output projection + fc
    dim3 ggrid(DD / 64, NROWS / 64);
    gemm_single<<<ggrid, 256>>>(ctx, wc, bc, out);
}

// round 9
// speedup vs baseline: 2.4932x; 1.1071x over previous
#include <cuda_runtime.h>
#include <cuda_fp16.h>
#include <cstdint>

#define BB 2
#define SS 2048
#define DD 256
#define HH 8
#define DH 32
#define NROWS (BB*SS)   // 4096

// Scratch (device globals: no allocation allowed)
__device__ float  g_q[NROWS*DD];
__device__ float  g_k[NROWS*DD];
__device__ float  g_v[NROWS*DD];
__device__ __half g_qh[NROWS*DD];
__device__ __half g_kh[NROWS*DD];
__device__ float  g_ctx[NROWS*DD];
__device__ float2 g_sq[2*NROWS*HH];  // {tanh^2, cosh^2}: [0..)=q rows, [NROWS*HH..)=k rows
__device__ float  g_wc[DD*DD];
__device__ float  g_bc[DD];

typedef unsigned long long u64;

// ---- Blackwell packed f32x2 helpers ----
__device__ __forceinline__ u64 ffma2(u64 a, u64 b, u64 c){
    u64 d; asm("fma.rn.f32x2 %0, %1, %2, %3;" : "=l"(d) : "l"(a), "l"(b), "l"(c)); return d;
}
__device__ __forceinline__ u64 pack2(float x, float y){
    u64 r; asm("mov.b64 %0, {%1, %2};" : "=l"(r) : "f"(x), "f"(y)); return r;
}
__device__ __forceinline__ float2 unpack2(u64 a){
    float2 f; asm("mov.b64 {%0, %1}, %2;" : "=f"(f.x), "=f"(f.y) : "l"(a)); return f;
}

// ---- f16 mma helpers ----
__device__ __forceinline__ uint32_t h2(float lo, float hi){
    uint32_t r; asm("cvt.rn.f16x2.f32 %0, %1, %2;" : "=r"(r) : "f"(hi), "f"(lo)); return r;
}
__device__ __forceinline__ void mma_f16(float (&c)[4], const uint32_t (&a)[4], const uint32_t (&b)[2]){
    asm volatile("mma.sync.aligned.m16n8k16.row.col.f32.f16.f16.f32 "
        "{%0,%1,%2,%3}, {%4,%5,%6,%7}, {%8,%9}, {%0,%1,%2,%3};"
        : "+f"(c[0]), "+f"(c[1]), "+f"(c[2]), "+f"(c[3])
        : "r"(a[0]), "r"(a[1]), "r"(a[2]), "r"(a[3]), "r"(b[0]), "r"(b[1]));
}
__device__ __forceinline__ float ex2(float x){
    float r; asm("ex2.approx.f32 %0, %1;" : "=f"(r) : "f"(x)); return r;
}

// ---------------------------------------------------------------------------
// SIMT fp32 GEMM (proven): C[m,n] = sum_k A[m,k]*W[n,k] + bias[n]
// ---------------------------------------------------------------------------
__device__ __forceinline__ void gemm_body(
    const float* __restrict__ A, const float* __restrict__ W,
    const float* __restrict__ bias, float* __restrict__ C,
    int m0, int n0)
{
    __shared__ __align__(16) float As[16][68];
    __shared__ __align__(16) float Bs[16][68];

    const int tid = threadIdx.x;
    const int lr = tid >> 2;
    const int lv = tid & 3;
    const int tx = tid & 15;
    const int ty = tid >> 4;

    u64 c2[4][2];
    #pragma unroll
    for (int r = 0; r < 4; r++) { c2[r][0] = 0ull; c2[r][1] = 0ull; }

    for (int k0 = 0; k0 < DD; k0 += 16) {
        float4 av = *(const float4*)&A[(m0 + lr) * DD + k0 + lv * 4];
        float4 bv = *(const float4*)&W[(n0 + lr) * DD + k0 + lv * 4];
        __syncthreads();
        As[lv*4+0][lr] = av.x; As[lv*4+1][lr] = av.y;
        As[lv*4+2][lr] = av.z; As[lv*4+3][lr] = av.w;
        Bs[lv*4+0][lr] = bv.x; Bs[lv*4+1][lr] = bv.y;
        Bs[lv*4+2][lr] = bv.z; Bs[lv*4+3][lr] = bv.w;
        __syncthreads();
        #pragma unroll
        for (int kk = 0; kk < 16; kk++) {
            float4 a4 = *(const float4*)&As[kk][ty * 4];
            ulonglong2 bp = *(const ulonglong2*)&Bs[kk][tx * 4];
            u64 a0 = pack2(a4.x, a4.x);
            u64 a1 = pack2(a4.y, a4.y);
            u64 a2 = pack2(a4.z, a4.z);
            u64 a3 = pack2(a4.w, a4.w);
            c2[0][0] = ffma2(a0, bp.x, c2[0][0]); c2[0][1] = ffma2(a0, bp.y, c2[0][1]);
            c2[1][0] = ffma2(a1, bp.x, c2[1][0]); c2[1][1] = ffma2(a1, bp.y, c2[1][1]);
            c2[2][0] = ffma2(a2, bp.x, c2[2][0]); c2[2][1] = ffma2(a2, bp.y, c2[2][1]);
            c2[3][0] = ffma2(a3, bp.x, c2[3][0]); c2[3][1] = ffma2(a3, bp.y, c2[3][1]);
        }
    }

    const int n = n0 + tx * 4;
    float4 bb = *(const float4*)&bias[n];
    #pragma unroll
    for (int r = 0; r < 4; r++) {
        float2 lo = unpack2(c2[r][0]);
        float2 hi = unpack2(c2[r][1]);
        float4 o;
        o.x = lo.x + bb.x; o.y = lo.y + bb.y;
        o.z = hi.x + bb.z; o.w = hi.y + bb.w;
        *(float4*)&C[(m0 + ty*4 + r) * DD + n] = o;
    }
}

struct QKVArgs {
    const float *Wq, *bq, *Wk, *bk, *Wv, *bv;
    float *q, *k, *v;
};

__global__ __launch_bounds__(256) void gemm_qkv(const float* __restrict__ x, QKVArgs a)
{
    const float* W; const float* b; float* C;
    if (blockIdx.z == 0)      { W = a.Wq; b = a.bq; C = a.q; }
    else if (blockIdx.z == 1) { W = a.Wk; b = a.bk; C = a.k; }
    else                      { W = a.Wv; b = a.bv; C = a.v; }
    gemm_body(x, W, b, C, blockIdx.y * 64, blockIdx.x * 64);
}

__global__ __launch_bounds__(256) void gemm_single(
    const float* __restrict__ A, const float* __restrict__ W,
    const float* __restrict__ bias, float* __restrict__ C)
{
    gemm_body(A, W, bias, C, blockIdx.y * 64, blockIdx.x * 64);
}

// ---------------------------------------------------------------------------
// Wcomb = Wfc @ Wo, bcomb = Wfc @ bo + bfc  (fuses the two output GEMMs)
// ---------------------------------------------------------------------------
__global__ __launch_bounds__(256) void wcomb_kernel(
    const float* __restrict__ Wfc, const float* __restrict__ Wo,
    float* __restrict__ Wc)
{
    __shared__ float wf[DD];
    const int n = blockIdx.x;
    const int kx = threadIdx.x;
    wf[kx] = Wfc[n * DD + kx];
    __syncthreads();
    float a0 = 0.f, a1 = 0.f, a2 = 0.f, a3 = 0.f;
    #pragma unroll 4
    for (int j = 0; j < DD; j += 4) {
        a0 = fmaf(wf[j+0], Wo[(j+0) * DD + kx], a0);
        a1 = fmaf(wf[j+1], Wo[(j+1) * DD + kx], a1);
        a2 = fmaf(wf[j+2], Wo[(j+2) * DD + kx], a2);
        a3 = fmaf(wf[j+3], Wo[(j+3) * DD + kx], a3);
    }
    Wc[n * DD + kx] = (a0 + a1) + (a2 + a3);
}

__global__ __launch_bounds__(256) void bcomb_kernel(
    const float* __restrict__ Wfc, const float* __restrict__ bo,
    const float* __restrict__ bfc, float* __restrict__ bc)
{
    const int n = threadIdx.x;
    float acc = bfc[n];
    for (int j = 0; j < DD; j++) acc = fmaf(Wfc[n * DD + j], bo[j], acc);
    bc[n] = acc;
}

// ---------------------------------------------------------------------------
// expmap0 for q and k (blockIdx.y selects tensor). Emits fp16 mapped vectors
// (the only consumer is the fp16 attention) + {tanh^2, cosh^2} constants.
// ---------------------------------------------------------------------------
__global__ __launch_bounds__(256) void expmap_kernel(
    const float* __restrict__ q, const float* __restrict__ k,
    __half* __restrict__ qh, __half* __restrict__ kh, float2* __restrict__ sq)
{
    const float* p = blockIdx.y ? k : q;
    __half* p16    = blockIdx.y ? kh : qh;
    float2* so = sq + blockIdx.y * (NROWS*HH);
    const int row  = blockIdx.x;
    const int h    = threadIdx.x >> 5;
    const int lane = threadIdx.x & 31;
    const int idx  = row * DD + h * DH + lane;
    float v = p[idx];
    float s = v * v;
    #pragma unroll
    for (int o = 16; o; o >>= 1) s += __shfl_xor_sync(0xffffffffu, s, o);
    float n2  = fmaxf(s, 1e-12f);
    float nrm = sqrtf(n2);
    float t   = tanhf(nrm);
    p16[idx] = __float2half(v * (t / nrm));
    if (lane == 0) {
        float ch = coshf(nrm);
        so[row * HH + h] = make_float2(t * t, ch * ch);
    }
}

// ---------------------------------------------------------------------------
// Attention: fp16 mma (m16n8k16) for BOTH S = QK^T and O += P V.
// fp16 has the same 10-bit mantissa as tf32 and q,k in (-1,1): S precision
// is unchanged vs 1-pass tf32, at half the mma count and no in-loop cvt.
//   u = cosh(dist) = 1 + (qq + kk - 2 qk) * (2 ch2_q ch2_k)
//   w = g^(-a), g = u + sqrt(u^2-1); for u >= 30, g ~= 2u with w-error
//   <= a/(4u^2) <= 4.9e-5, so w = ex2(fma(lg2(min(u,UCLIP)), -a, -a))
//   (2*UCLIP = GMAX exactly, so the reference clip folds into the min).
//   A warp vote falls back to the exact formula if any u < 30 (in practice
//   never: u < 30 needs ||q-k|| ~ 2e-4 between independent projections).
// ---------------------------------------------------------------------------
#define KT 64
#define SC_EXP 0.17677669529663689f   /* 1/sqrt(32) */
#define NEG_A  (-0.17677669529663689f)
#define UCLIP  99999.5f               /* (1+T)/(1-T) = 2*UCLIP, T = 1-1e-5 */
#define WCLIP  0.11558618f
#define UAPPROX 30.0f

__global__ __launch_bounds__(128) void attn_kernel(
    const __half* __restrict__ qh16, const __half* __restrict__ kh16,
    const float* __restrict__ v, const float2* __restrict__ sq2,
    float* __restrict__ ctx)
{
    __shared__ __align__(16) __half sKh[KT][40];
    __shared__ __align__(16) float  sV[KT][36];
    __shared__ float2 sKC[KT];

    const int b   = blockIdx.z;
    const int h   = blockIdx.y;
    const int q0  = blockIdx.x * 128;
    const int tid = threadIdx.x;
    const int w   = tid >> 5;
    const int lane= tid & 31;
    const int g   = lane >> 2;
    const int t4  = lane & 3;
    const int wrow = w * 32;

    const float2* cq = sq2;               // q-side {tanh^2, cosh^2}
    const float2* ck = sq2 + NROWS*HH;    // k-side

    // per-thread row constants (rows wrow + m*16 + rh*8 + g)
    float qqr[4], fr2[4];
    #pragma unroll
    for (int m = 0; m < 2; m++)
        #pragma unroll
        for (int rh = 0; rh < 2; rh++) {
            int r = b*SS + q0 + wrow + m*16 + rh*8 + g;
            float2 c = cq[r*HH + h];
            qqr[m*2+rh] = c.x;
            fr2[m*2+rh] = 2.0f * c.y;
        }

    // Q fragments: f16 m16n8k16 A layout, 2 k-chunks of 16 dims.
    uint32_t qf[2][2][4];
    #pragma unroll
    for (int m = 0; m < 2; m++)
        #pragma unroll
        for (int ks = 0; ks < 2; ks++) {
            int r0 = b*SS + q0 + wrow + m*16 + g;
            int c0 = h*DH + ks*16 + 2*t4;
            qf[m][ks][0] = *(const uint32_t*)&qh16[r0*DD + c0];
            qf[m][ks][1] = *(const uint32_t*)&qh16[(r0+8)*DD + c0];
            qf[m][ks][2] = *(const uint32_t*)&qh16[r0*DD + c0 + 8];
            qf[m][ks][3] = *(const uint32_t*)&qh16[(r0+8)*DD + c0 + 8];
        }

    float O[2][4][4];
    #pragma unroll
    for (int m = 0; m < 2; m++)
        #pragma unroll
        for (int nt = 0; nt < 4; nt++)
            #pragma unroll
            for (int r = 0; r < 4; r++) O[m][nt][r] = 0.0f;
    float lacc[4] = {0.f, 0.f, 0.f, 0.f};

    #pragma unroll 1
    for (int t0 = 0; t0 < SS; t0 += KT) {
        __syncthreads();
        // K tile: 64 rows x 32 halves (uint4 = 8 halves; 2 per thread)
        #pragma unroll
        for (int i = 0; i < 2; i++) {
            int l = tid + i*128;          // 0..255
            int row = l >> 2, j = l & 3;
            *(uint4*)&sKh[row][j*8] = *(const uint4*)&kh16[(b*SS+t0+row)*DD + h*DH + j*8];
        }
        // V tile: 64 rows x 32 floats
        #pragma unroll
        for (int i = 0; i < 4; i++) {
            int l = tid + i*128;          // 0..511
            int row = l >> 3, j = l & 7;
            *(float4*)&sV[row][j*4] = *(const float4*)&v[(b*SS+t0+row)*DD + h*DH + j*4];
        }
        if (tid < KT) sKC[tid] = ck[(b*SS + t0 + tid)*HH + h];
        __syncthreads();

        #pragma unroll 1
        for (int half = 0; half < 2; half++) {
            // ---- S = Q K^T for keys [half*32, half*32+32), fp16 k16 ----
            float S[2][4][4];
            #pragma unroll
            for (int m = 0; m < 2; m++)
                #pragma unroll
                for (int nt = 0; nt < 4; nt++)
                    #pragma unroll
                    for (int r = 0; r < 4; r++) S[m][nt][r] = 0.0f;

            #pragma unroll
            for (int nt = 0; nt < 4; nt++) {
                int kr = half*32 + nt*8 + g;
                #pragma unroll
                for (int ks = 0; ks < 2; ks++) {
                    uint32_t bb[2];
                    bb[0] = *(const uint32_t*)&sKh[kr][ks*16 + 2*t4];
                    bb[1] = *(const uint32_t*)&sKh[kr][ks*16 + 8 + 2*t4];
                    mma_f16(S[0][nt], qf[0][ks], bb);
                    mma_f16(S[1][nt], qf[1][ks], bb);
                }
            }

            // ---- qk -> u = cosh(dist) (store in S), vote on rare path ----
            float2 kcr[8];
            #pragma unroll
            for (int nt = 0; nt < 4; nt++)
                #pragma unroll
                for (int rb = 0; rb < 2; rb++)
                    kcr[nt*2+rb] = sKC[half*32 + nt*8 + 2*t4 + rb];

            bool need = false;
            #pragma unroll
            for (int m = 0; m < 2; m++)
                #pragma unroll
                for (int nt = 0; nt < 4; nt++)
                    #pragma unroll
                    for (int r = 0; r < 4; r++) {
                        int ci   = nt*2 + (r & 1);
                        int ridx = m*2 + (r >> 1);
                        float nm = fmaf(-2.0f, S[m][nt][r], qqr[ridx] + kcr[ci].x);
                        float u  = fmaf(nm, fr2[ridx] * kcr[ci].y, 1.0f);
                        need |= (u < UAPPROX);
                        S[m][nt][r] = u;
                    }

            if (__any_sync(0xffffffffu, need)) {
                // exact path (rare): g = u + sqrt(u^2-1), explicit clip
                #pragma unroll
                for (int m = 0; m < 2; m++)
                    #pragma unroll
                    for (int nt = 0; nt < 4; nt++)
                        #pragma unroll
                        for (int r = 0; r < 4; r++) {
                            int ridx = m*2 + (r >> 1);
                            float u = S[m][nt][r];
                            float w_ = WCLIP;
                            if (u < UCLIP) {
                                float t = fmaf(u, u, -1.0f);
                                t = fmaxf(t, 0.0f);
                                float gg = u + t * rsqrtf(fmaxf(t, 1e-30f));
                                gg = fmaxf(gg, 1.0f);
                                w_ = ex2(NEG_A * __log2f(gg) / 0.17677669529663689f * SC_EXP);
                                w_ = ex2(-SC_EXP * __log2f(gg));
                            }
                            lacc[ridx] += w_;
                            S[m][nt][r] = w_;
                        }
            } else {
                // approx path: w = (2u)^-a = ex2(fma(lg2(min(u,UCLIP)),-a,-a))
                #pragma unroll
                for (int m = 0; m < 2; m++)
                    #pragma unroll
                    for (int nt = 0; nt < 4; nt++)
                        #pragma unroll
                        for (int r = 0; r < 4; r++) {
                            int ridx = m*2 + (r >> 1);
                            float um = fminf(S[m][nt][r], UCLIP);
                            float w_ = ex2(fmaf(__log2f(um), NEG_A, NEG_A));
                            lacc[ridx] += w_;
                            S[m][nt][r] = w_;
                        }
            }

            // ---- pack P into f16 A-fragments (register-only) ----
            uint32_t pa[2][2][4];
            #pragma unroll
            for (int m = 0; m < 2; m++)
                #pragma unroll
                for (int kc2 = 0; kc2 < 2; kc2++) {
                    int nt0 = 2*kc2, nt1 = 2*kc2 + 1;
                    pa[m][kc2][0] = h2(S[m][nt0][0], S[m][nt0][1]);
                    pa[m][kc2][1] = h2(S[m][nt0][2], S[m][nt0][3]);
                    pa[m][kc2][2] = h2(S[m][nt1][0], S[m][nt1][1]);
                    pa[m][kc2][3] = h2(S[m][nt1][2], S[m][nt1][3]);
                }

            // ---- O += P V  (fp16 m16n8k16; V packed from fp32 smem) ----
            #pragma unroll
            for (int kc2 = 0; kc2 < 2; kc2++) {
                int kb = half*32 + kc2*16;
                #pragma unroll
                for (int nt = 0; nt < 4; nt++) {
                    int col = nt*8 + g;
                    uint32_t bb[2];
                    bb[0] = h2(sV[kb + 2*t4][col],     sV[kb + 2*t4 + 1][col]);
                    bb[1] = h2(sV[kb + 8 + 2*t4][col], sV[kb + 9 + 2*t4][col]);
                    mma_f16(O[0][nt], pa[0][kc2], bb);
                    mma_f16(O[1][nt], pa[1][kc2], bb);
                }
            }
        }
    }

    // ---- epilogue: reduce l over quad, normalize, store ----
    #pragma unroll
    for (int i = 0; i < 4; i++) {
        lacc[i] += __shfl_xor_sync(0xffffffffu, lacc[i], 1);
        lacc[i] += __shfl_xor_sync(0xffffffffu, lacc[i], 2);
        lacc[i] = __fdividef(1.0f, lacc[i]);
    }
    #pragma unroll
    for (int m = 0; m < 2; m++)
        #pragma unroll
        for (int rh = 0; rh < 2; rh++) {
            int grow = b*SS + q0 + wrow + m*16 + rh*8 + g;
            float rl = lacc[m*2 + rh];
            #pragma unroll
            for (int nt = 0; nt < 4; nt++) {
                float2 o;
                o.x = O[m][nt][rh*2 + 0] * rl;
                o.y = O[m][nt][rh*2 + 1] * rl;
                *(float2*)&ctx[grow*DD + h*DH + nt*8 + 2*t4] = o;
            }
        }
}

// ---------------------------------------------------------------------------

extern "C" void kernel_launch(void* const* d_in, const int* in_sizes, int n_in,
                              void* d_out, int out_size)
{
    const float* x   = (const float*)d_in[0];
    const float* Wq  = (const float*)d_in[1];
    const float* bq  = (const float*)d_in[2];
    const float* Wk  = (const float*)d_in[3];
    const float* bk  = (const float*)d_in[4];
    const float* Wv  = (const float*)d_in[5];
    const float* bv  = (const float*)d_in[6];
    const float* Wo  = (const float*)d_in[7];
    const float* bo  = (const float*)d_in[8];
    const float* Wfc = (const float*)d_in[9];
    const float* bfc = (const float*)d_in[10];
    float* out = (float*)d_out;

    float *q, *k, *v, *ctx, *wc, *bc;
    __half *qh, *kh;
    float2* sq;
    cudaGetSymbolAddress((void**)&q,   g_q);
    cudaGetSymbolAddress((void**)&k,   g_k);
    cudaGetSymbolAddress((void**)&v,   g_v);
    cudaGetSymbolAddress((void**)&qh,  g_qh);
    cudaGetSymbolAddress((void**)&kh,  g_kh);
    cudaGetSymbolAddress((void**)&ctx, g_ctx);
    cudaGetSymbolAddress((void**)&sq,  g_sq);
    cudaGetSymbolAddress((void**)&wc,  g_wc);
    cudaGetSymbolAddress((void**)&bc,  g_bc);

    // Combined output weights (fuses Wo and Wfc GEMMs)
    wcomb_kernel<<<DD, DD>>>(Wfc, Wo, wc);
    bcomb_kernel<<<1, DD>>>(Wfc, bo, bfc, bc);

    // Q/K/V projections in one launch
    QKVArgs a { Wq, bq, Wk, bk, Wv, bv, q, k, v };
    dim3 qkvgrid(DD / 64, NROWS / 64, 3);
    gemm_qkv<<<qkvgrid, 256>>>(x, a);

    // expmap0 on q and k -> fp16 + constants
    dim3 egrid(NROWS, 2);
    expmap_kernel<<<egrid, 256>>>(q, k, qh, kh, sq);

    // attention (fp16 S and PV)
    dim3 agrid(SS / 128, HH, BB);
    attn_kernel<<<agrid, 128>>>(qh, kh, v, sq, ctx);

    // fused output projection + fc
    dim3 ggrid(DD / 64, NROWS / 64);
    gemm_single<<<ggrid, 256>>>(ctx, wc, bc, out);
}

// round 11
// speedup vs baseline: 2.6276x; 1.0539x over previous
#include <cuda_runtime.h>
#include <cuda_fp16.h>
#include <cstdint>

#define BB 2
#define SS 2048
#define DD 256
#define HH 8
#define DH 32
#define NROWS (BB*SS)   // 4096

// Scratch (device globals: no allocation allowed)
__device__ float  g_q[NROWS*DD];
__device__ float  g_k[NROWS*DD];
__device__ float  g_v[NROWS*DD];
__device__ __half g_qh[NROWS*DD];
__device__ __half g_kh[NROWS*DD];
__device__ __half g_vt[NROWS*DD];    // V fp16, transposed per (b,h): [(b*HH+h)*DH + c][t]
__device__ float  g_ctx[NROWS*DD];
__device__ float2 g_sqq[NROWS*HH];   // q {tanh^2, cosh^2}, h-major: [h*NROWS + r]
__device__ float2 g_sqk[NROWS*HH];   // k likewise
__device__ float  g_wc[DD*DD];
__device__ float  g_bc[DD];

typedef unsigned long long u64;

// ---- Blackwell packed f32x2 helpers ----
__device__ __forceinline__ u64 ffma2(u64 a, u64 b, u64 c){
    u64 d; asm("fma.rn.f32x2 %0, %1, %2, %3;" : "=l"(d) : "l"(a), "l"(b), "l"(c)); return d;
}
__device__ __forceinline__ u64 pack2(float x, float y){
    u64 r; asm("mov.b64 %0, {%1, %2};" : "=l"(r) : "f"(x), "f"(y)); return r;
}
__device__ __forceinline__ float2 unpack2(u64 a){
    float2 f; asm("mov.b64 {%0, %1}, %2;" : "=f"(f.x), "=f"(f.y) : "l"(a)); return f;
}

// ---- f16 mma / cp.async helpers ----
__device__ __forceinline__ uint32_t h2(float lo, float hi){
    uint32_t r; asm("cvt.rn.f16x2.f32 %0, %1, %2;" : "=r"(r) : "f"(hi), "f"(lo)); return r;
}
__device__ __forceinline__ void mma_f16(float (&c)[4], const uint32_t (&a)[4], const uint32_t (&b)[2]){
    asm volatile("mma.sync.aligned.m16n8k16.row.col.f32.f16.f16.f32 "
        "{%0,%1,%2,%3}, {%4,%5,%6,%7}, {%8,%9}, {%0,%1,%2,%3};"
        : "+f"(c[0]), "+f"(c[1]), "+f"(c[2]), "+f"(c[3])
        : "r"(a[0]), "r"(a[1]), "r"(a[2]), "r"(a[3]), "r"(b[0]), "r"(b[1]));
}
__device__ __forceinline__ float ex2(float x){
    float r; asm("ex2.approx.f32 %0, %1;" : "=f"(r) : "f"(x)); return r;
}
__device__ __forceinline__ void cpa16(uint32_t dst, const void* src){
    asm volatile("cp.async.ca.shared.global [%0], [%1], 16;" :: "r"(dst), "l"(src));
}
#define CP_COMMIT() asm volatile("cp.async.commit_group;" ::: "memory")
#define CP_WAIT0()  asm volatile("cp.async.wait_group 0;" ::: "memory")

// ---------------------------------------------------------------------------
// SIMT fp32 GEMM (proven): C[m,n] = sum_k A[m,k]*W[n,k] + bias[n]
// ---------------------------------------------------------------------------
__device__ __forceinline__ void gemm_body(
    const float* __restrict__ A, const float* __restrict__ W,
    const float* __restrict__ bias, float* __restrict__ C,
    int m0, int n0)
{
    __shared__ __align__(16) float As[16][68];
    __shared__ __align__(16) float Bs[16][68];

    const int tid = threadIdx.x;
    const int lr = tid >> 2;
    const int lv = tid & 3;
    const int tx = tid & 15;
    const int ty = tid >> 4;

    u64 c2[4][2];
    #pragma unroll
    for (int r = 0; r < 4; r++) { c2[r][0] = 0ull; c2[r][1] = 0ull; }

    for (int k0 = 0; k0 < DD; k0 += 16) {
        float4 av = *(const float4*)&A[(m0 + lr) * DD + k0 + lv * 4];
        float4 bv = *(const float4*)&W[(n0 + lr) * DD + k0 + lv * 4];
        __syncthreads();
        As[lv*4+0][lr] = av.x; As[lv*4+1][lr] = av.y;
        As[lv*4+2][lr] = av.z; As[lv*4+3][lr] = av.w;
        Bs[lv*4+0][lr] = bv.x; Bs[lv*4+1][lr] = bv.y;
        Bs[lv*4+2][lr] = bv.z; Bs[lv*4+3][lr] = bv.w;
        __syncthreads();
        #pragma unroll
        for (int kk = 0; kk < 16; kk++) {
            float4 a4 = *(const float4*)&As[kk][ty * 4];
            ulonglong2 bp = *(const ulonglong2*)&Bs[kk][tx * 4];
            u64 a0 = pack2(a4.x, a4.x);
            u64 a1 = pack2(a4.y, a4.y);
            u64 a2 = pack2(a4.z, a4.z);
            u64 a3 = pack2(a4.w, a4.w);
            c2[0][0] = ffma2(a0, bp.x, c2[0][0]); c2[0][1] = ffma2(a0, bp.y, c2[0][1]);
            c2[1][0] = ffma2(a1, bp.x, c2[1][0]); c2[1][1] = ffma2(a1, bp.y, c2[1][1]);
            c2[2][0] = ffma2(a2, bp.x, c2[2][0]); c2[2][1] = ffma2(a2, bp.y, c2[2][1]);
            c2[3][0] = ffma2(a3, bp.x, c2[3][0]); c2[3][1] = ffma2(a3, bp.y, c2[3][1]);
        }
    }

    const int n = n0 + tx * 4;
    float4 bb = *(const float4*)&bias[n];
    #pragma unroll
    for (int r = 0; r < 4; r++) {
        float2 lo = unpack2(c2[r][0]);
        float2 hi = unpack2(c2[r][1]);
        float4 o;
        o.x = lo.x + bb.x; o.y = lo.y + bb.y;
        o.z = hi.x + bb.z; o.w = hi.y + bb.w;
        *(float4*)&C[(m0 + ty*4 + r) * DD + n] = o;
    }
}

struct QKVArgs {
    const float *Wq, *bq, *Wk, *bk, *Wv, *bv;
    float *q, *k, *v;
};

__global__ __launch_bounds__(256) void gemm_qkv(const float* __restrict__ x, QKVArgs a)
{
    const float* W; const float* b; float* C;
    if (blockIdx.z == 0)      { W = a.Wq; b = a.bq; C = a.q; }
    else if (blockIdx.z == 1) { W = a.Wk; b = a.bk; C = a.k; }
    else                      { W = a.Wv; b = a.bv; C = a.v; }
    gemm_body(x, W, b, C, blockIdx.y * 64, blockIdx.x * 64);
}

__global__ __launch_bounds__(256) void gemm_single(
    const float* __restrict__ A, const float* __restrict__ W,
    const float* __restrict__ bias, float* __restrict__ C)
{
    gemm_body(A, W, bias, C, blockIdx.y * 64, blockIdx.x * 64);
}

// ---------------------------------------------------------------------------
// Wcomb = Wfc @ Wo, bcomb = Wfc @ bo + bfc  (fuses the two output GEMMs)
// ---------------------------------------------------------------------------
__global__ __launch_bounds__(256) void wcomb_kernel(
    const float* __restrict__ Wfc, const float* __restrict__ Wo,
    float* __restrict__ Wc)
{
    __shared__ float wf[DD];
    const int n = blockIdx.x;
    const int kx = threadIdx.x;
    wf[kx] = Wfc[n * DD + kx];
    __syncthreads();
    float a0 = 0.f, a1 = 0.f, a2 = 0.f, a3 = 0.f;
    #pragma unroll 4
    for (int j = 0; j < DD; j += 4) {
        a0 = fmaf(wf[j+0], Wo[(j+0) * DD + kx], a0);
        a1 = fmaf(wf[j+1], Wo[(j+1) * DD + kx], a1);
        a2 = fmaf(wf[j+2], Wo[(j+2) * DD + kx], a2);
        a3 = fmaf(wf[j+3], Wo[(j+3) * DD + kx], a3);
    }
    Wc[n * DD + kx] = (a0 + a1) + (a2 + a3);
}

__global__ __launch_bounds__(256) void bcomb_kernel(
    const float* __restrict__ Wfc, const float* __restrict__ bo,
    const float* __restrict__ bfc, float* __restrict__ bc)
{
    const int n = threadIdx.x;
    float acc = bfc[n];
    for (int j = 0; j < DD; j++) acc = fmaf(Wfc[n * DD + j], bo[j], acc);
    bc[n] = acc;
}

// ---------------------------------------------------------------------------
// expmap0 for q and k (blockIdx.y selects tensor). Emits fp16 mapped vectors
// + {tanh^2, cosh^2} in h-major layout [h*NROWS + row] (contiguous per head).
// ---------------------------------------------------------------------------
__global__ __launch_bounds__(256) void expmap_kernel(
    const float* __restrict__ q, const float* __restrict__ k,
    __half* __restrict__ qh, __half* __restrict__ kh,
    float2* __restrict__ sqq, float2* __restrict__ sqk)
{
    const float* p = blockIdx.y ? k : q;
    __half* p16    = blockIdx.y ? kh : qh;
    float2* so     = blockIdx.y ? sqk : sqq;
    const int row  = blockIdx.x;
    const int h    = threadIdx.x >> 5;
    const int lane = threadIdx.x & 31;
    const int idx  = row * DD + h * DH + lane;
    float v = p[idx];
    float s = v * v;
    #pragma unroll
    for (int o = 16; o; o >>= 1) s += __shfl_xor_sync(0xffffffffu, s, o);
    float n2  = fmaxf(s, 1e-12f);
    float nrm = sqrtf(n2);
    float t   = tanhf(nrm);
    p16[idx] = __float2half(v * (t / nrm));
    if (lane == 0) {
        float ch = coshf(nrm);
        so[h * NROWS + row] = make_float2(t * t, ch * ch);
    }
}

// ---------------------------------------------------------------------------
// V -> fp16 transposed per (b,h): vt[((b*HH+h)*DH + c)*SS + t]
// ---------------------------------------------------------------------------
__global__ __launch_bounds__(256) void vconv_kernel(
    const float* __restrict__ v, __half* __restrict__ vt)
{
    __shared__ float sv[64][33];
    const int b  = blockIdx.z, h = blockIdx.y, t0 = blockIdx.x * 64;
    const int tid = threadIdx.x;
    #pragma unroll
    for (int i = 0; i < 8; i++) {
        int l = tid + i*256;
        int row = l >> 5, c = l & 31;
        sv[row][c] = v[(b*SS + t0 + row)*DD + h*DH + c];
    }
    __syncthreads();
    const int c = tid >> 3, j = tid & 7;
    uint32_t o[4];
    #pragma unroll
    for (int r = 0; r < 4; r++)
        o[r] = h2(sv[j*8 + 2*r][c], sv[j*8 + 2*r + 1][c]);
    *(uint4*)&vt[((b*HH + h)*DH + c)*SS + t0 + j*8] = *(uint4*)o;
}

// ---------------------------------------------------------------------------
// Attention: fp16 mma for S = QK^T and O += P V, cp.async double-buffered.
//   u = cosh(dist) = 1 + (qq + kk - 2 qk) * (2 ch2_q ch2_k)
//   w = g^(-a), g = u + sqrt(u^2-1); for u >= 30, g ~= 2u (w-err <= 4.9e-5):
//   w = ex2(fma(lg2(min(u,UCLIP)), -a, -a)); 2*UCLIP = (1+T)/(1-T) exactly.
// V is pre-transposed fp16: PV B-frags are direct LDS.32 of packed pairs.
// ---------------------------------------------------------------------------
#define KT 64
#define SC_EXP 0.17677669529663689f
#define NEG_A  (-0.17677669529663689f)
#define UCLIP  99999.5f
#define WCLIP  0.11558618f
#define UAPPROX 30.0f

__global__ __launch_bounds__(128) void attn_kernel(
    const __half* __restrict__ qh16, const __half* __restrict__ kh16,
    const __half* __restrict__ vt, const float2* __restrict__ cq,
    const float2* __restrict__ ckc, float* __restrict__ ctx)
{
    __shared__ __align__(16) __half sKh[2][KT][40];
    __shared__ __align__(16) __half sVt[2][DH][72];
    __shared__ __align__(16) float2 sKC[2][KT];

    const int b   = blockIdx.z;
    const int h   = blockIdx.y;
    const int q0  = blockIdx.x * 128;
    const int tid = threadIdx.x;
    const int w   = tid >> 5;
    const int lane= tid & 31;
    const int g   = lane >> 2;
    const int t4  = lane & 3;
    const int wrow = w * 32;

    const __half* vtb = vt + (size_t)((b*HH + h)*DH) * SS;
    const float2* kcb = ckc + h*NROWS + b*SS;

    const uint32_t sKh_a = (uint32_t)__cvta_generic_to_shared(&sKh[0][0][0]);
    const uint32_t sVt_a = (uint32_t)__cvta_generic_to_shared(&sVt[0][0][0]);
    const uint32_t sKC_a = (uint32_t)__cvta_generic_to_shared(&sKC[0][0]);

    // per-thread row constants (rows wrow + m*16 + rh*8 + g)
    float qqr[4], fr2[4];
    #pragma unroll
    for (int m = 0; m < 2; m++)
        #pragma unroll
        for (int rh = 0; rh < 2; rh++) {
            int r = b*SS + q0 + wrow + m*16 + rh*8 + g;
            float2 c = cq[h*NROWS + r];
            qqr[m*2+rh] = c.x;
            fr2[m*2+rh] = 2.0f * c.y;
        }

    // Q fragments: f16 m16n8k16 A layout, 2 k-chunks of 16 dims.
    uint32_t qf[2][2][4];
    #pragma unroll
    for (int m = 0; m < 2; m++)
        #pragma unroll
        for (int ks = 0; ks < 2; ks++) {
            int r0 = b*SS + q0 + wrow + m*16 + g;
            int c0 = h*DH + ks*16 + 2*t4;
            qf[m][ks][0] = *(const uint32_t*)&qh16[r0*DD + c0];
            qf[m][ks][1] = *(const uint32_t*)&qh16[(r0+8)*DD + c0];
            qf[m][ks][2] = *(const uint32_t*)&qh16[r0*DD + c0 + 8];
            qf[m][ks][3] = *(const uint32_t*)&qh16[(r0+8)*DD + c0 + 8];
        }

    float O[2][4][4];
    #pragma unroll
    for (int m = 0; m < 2; m++)
        #pragma unroll
        for (int nt = 0; nt < 4; nt++)
            #pragma unroll
            for (int r = 0; r < 4; r++) O[m][nt][r] = 0.0f;
    float lacc[4] = {0.f, 0.f, 0.f, 0.f};

    // tile loader (cp.async): K 256x16B, Vt 256x16B, KC 32x16B
    auto load_tile = [&](int t0, int s) {
        #pragma unroll
        for (int i = 0; i < 2; i++) {
            int l = tid + i*128;
            int row = l >> 2, j = l & 3;
            cpa16(sKh_a + ((s*KT + row)*40 + j*8)*2,
                  &kh16[(b*SS + t0 + row)*DD + h*DH + j*8]);
        }
        #pragma unroll
        for (int i = 0; i < 2; i++) {
            int l = tid + i*128;
            int c = l >> 3, j = l & 7;
            cpa16(sVt_a + ((s*DH + c)*72 + j*8)*2, &vtb[c*SS + t0 + j*8]);
        }
        if (tid < 32) cpa16(sKC_a + (s*KT + tid*2)*8, &kcb[t0 + tid*2]);
    };

    load_tile(0, 0);
    CP_COMMIT();

    #pragma unroll 1
    for (int it = 0; it < SS/KT; it++) {
        const int s = it & 1;
        CP_WAIT0();
        __syncthreads();
        if (it + 1 < SS/KT) {
            load_tile((it+1)*KT, s ^ 1);
            CP_COMMIT();
        }

        #pragma unroll 1
        for (int half = 0; half < 2; half++) {
            // ---- S = Q K^T for keys [half*32, half*32+32) ----
            float S[2][4][4];
            #pragma unroll
            for (int m = 0; m < 2; m++)
                #pragma unroll
                for (int nt = 0; nt < 4; nt++)
                    #pragma unroll
                    for (int r = 0; r < 4; r++) S[m][nt][r] = 0.0f;

            #pragma unroll
            for (int nt = 0; nt < 4; nt++) {
                int kr = half*32 + nt*8 + g;
                #pragma unroll
                for (int ks = 0; ks < 2; ks++) {
                    uint32_t bb[2];
                    bb[0] = *(const uint32_t*)&sKh[s][kr][ks*16 + 2*t4];
                    bb[1] = *(const uint32_t*)&sKh[s][kr][ks*16 + 8 + 2*t4];
                    mma_f16(S[0][nt], qf[0][ks], bb);
                    mma_f16(S[1][nt], qf[1][ks], bb);
                }
            }

            // ---- qk -> u = cosh(dist), vote on rare exact path ----
            float2 kcr[8];
            #pragma unroll
            for (int nt = 0; nt < 4; nt++)
                #pragma unroll
                for (int rb = 0; rb < 2; rb++)
                    kcr[nt*2+rb] = sKC[s][half*32 + nt*8 + 2*t4 + rb];

            bool need = false;
            #pragma unroll
            for (int m = 0; m < 2; m++)
                #pragma unroll
                for (int nt = 0; nt < 4; nt++)
                    #pragma unroll
                    for (int r = 0; r < 4; r++) {
                        int ci   = nt*2 + (r & 1);
                        int ridx = m*2 + (r >> 1);
                        float nm = fmaf(-2.0f, S[m][nt][r], qqr[ridx] + kcr[ci].x);
                        float u  = fmaf(nm, fr2[ridx] * kcr[ci].y, 1.0f);
                        need |= (u < UAPPROX);
                        S[m][nt][r] = u;
                    }

            if (__any_sync(0xffffffffu, need)) {
                #pragma unroll
                for (int m = 0; m < 2; m++)
                    #pragma unroll
                    for (int nt = 0; nt < 4; nt++)
                        #pragma unroll
                        for (int r = 0; r < 4; r++) {
                            int ridx = m*2 + (r >> 1);
                            float u = S[m][nt][r];
                            float w_ = WCLIP;
                            if (u < UCLIP) {
                                float t = fmaf(u, u, -1.0f);
                                t = fmaxf(t, 0.0f);
                                float gg = u + t * rsqrtf(fmaxf(t, 1e-30f));
                                gg = fmaxf(gg, 1.0f);
                                w_ = ex2(-SC_EXP * __log2f(gg));
                            }
                            lacc[ridx] += w_;
                            S[m][nt][r] = w_;
                        }
            } else {
                #pragma unroll
                for (int m = 0; m < 2; m++)
                    #pragma unroll
                    for (int nt = 0; nt < 4; nt++)
                        #pragma unroll
                        for (int r = 0; r < 4; r++) {
                            int ridx = m*2 + (r >> 1);
                            float um = fminf(S[m][nt][r], UCLIP);
                            float w_ = ex2(fmaf(__log2f(um), NEG_A, NEG_A));
                            lacc[ridx] += w_;
                            S[m][nt][r] = w_;
                        }
            }

            // ---- pack P into f16 A-fragments (register-only) ----
            uint32_t pa[2][2][4];
            #pragma unroll
            for (int m = 0; m < 2; m++)
                #pragma unroll
                for (int kc2 = 0; kc2 < 2; kc2++) {
                    int nt0 = 2*kc2, nt1 = 2*kc2 + 1;
                    pa[m][kc2][0] = h2(S[m][nt0][0], S[m][nt0][1]);
                    pa[m][kc2][1] = h2(S[m][nt0][2], S[m][nt0][3]);
                    pa[m][kc2][2] = h2(S[m][nt1][0], S[m][nt1][1]);
                    pa[m][kc2][3] = h2(S[m][nt1][2], S[m][nt1][3]);
                }

            // ---- O += P V  (B-frags: direct LDS.32 from transposed fp16 V) ----
            #pragma unroll
            for (int kc2 = 0; kc2 < 2; kc2++) {
                int kb = half*32 + kc2*16;
                #pragma unroll
                for (int nt = 0; nt < 4; nt++) {
                    int col = nt*8 + g;
                    uint32_t bb[2];
                    bb[0] = *(const uint32_t*)&sVt[s][col][kb + 2*t4];
                    bb[1] = *(const uint32_t*)&sVt[s][col][kb + 8 + 2*t4];
                    mma_f16(O[0][nt], pa[0][kc2], bb);
                    mma_f16(O[1][nt], pa[1][kc2], bb);
                }
            }
        }
        __syncthreads();
    }

    // ---- epilogue: reduce l over quad, normalize, store ----
    #pragma unroll
    for (int i = 0; i < 4; i++) {
        lacc[i] += __shfl_xor_sync(0xffffffffu, lacc[i], 1);
        lacc[i] += __shfl_xor_sync(0xffffffffu, lacc[i], 2);
        lacc[i] = __fdividef(1.0f, lacc[i]);
    }
    #pragma unroll
    for (int m = 0; m < 2; m++)
        #pragma unroll
        for (int rh = 0; rh < 2; rh++) {
            int grow = b*SS + q0 + wrow + m*16 + rh*8 + g;
            float rl = lacc[m*2 + rh];
            #pragma unroll
            for (int nt = 0; nt < 4; nt++) {
                float2 o;
                o.x = O[m][nt][rh*2 + 0] * rl;
                o.y = O[m][nt][rh*2 + 1] * rl;
                *(float2*)&ctx[grow*DD + h*DH + nt*8 + 2*t4] = o;
            }
        }
}

// ---------------------------------------------------------------------------

extern "C" void kernel_launch(void* const* d_in, const int* in_sizes, int n_in,
                              void* d_out, int out_size)
{
    const float* x   = (const float*)d_in[0];
    const float* Wq  = (const float*)d_in[1];
    const float* bq  = (const float*)d_in[2];
    const float* Wk  = (const float*)d_in[3];
    const float* bk  = (const float*)d_in[4];
    const float* Wv  = (const float*)d_in[5];
    const float* bv  = (const float*)d_in[6];
    const float* Wo  = (const float*)d_in[7];
    const float* bo  = (const float*)d_in[8];
    const float* Wfc = (const float*)d_in[9];
    const float* bfc = (const float*)d_in[10];
    float* out = (float*)d_out;

    float *q, *k, *v, *ctx, *wc, *bc;
    __half *qh, *kh, *vt;
    float2 *sqq, *sqk;
    cudaGetSymbolAddress((void**)&q,   g_q);
    cudaGetSymbolAddress((void**)&k,   g_k);
    cudaGetSymbolAddress((void**)&v,   g_v);
    cudaGetSymbolAddress((void**)&qh,  g_qh);
    cudaGetSymbolAddress((void**)&kh,  g_kh);
    cudaGetSymbolAddress((void**)&vt,  g_vt);
    cudaGetSymbolAddress((void**)&ctx, g_ctx);
    cudaGetSymbolAddress((void**)&sqq, g_sqq);
    cudaGetSymbolAddress((void**)&sqk, g_sqk);
    cudaGetSymbolAddress((void**)&wc,  g_wc);
    cudaGetSymbolAddress((void**)&bc,  g_bc);

    // Combined output weights (fuses Wo and Wfc GEMMs)
    wcomb_kernel<<<DD, DD>>>(Wfc, Wo, wc);
    bcomb_kernel<<<1, DD>>>(Wfc, bo, bfc, bc);

    // Q/K/V projections in one launch
    QKVArgs a { Wq, bq, Wk, bk, Wv, bv, q, k, v };
    dim3 qkvgrid(DD / 64, NROWS / 64, 3);
    gemm_qkv<<<qkvgrid, 256>>>(x, a);

    // expmap0 (q,k -> fp16 + constants) and V transpose/convert
    dim3 egrid(NROWS, 2);
    expmap_kernel<<<egrid, 256>>>(q, k, qh, kh, sqq, sqk);
    dim3 vgrid(SS / 64, HH, BB);
    vconv_kernel<<<vgrid, 256>>>(v, vt);

    // attention (fp16 mma, cp.async double-buffered)
    dim3 agrid(SS / 128, HH, BB);
    attn_kernel<<<agrid, 128>>>(qh, kh, vt, sqq, sqk, ctx);

    // fused output projection + fc
    dim3 ggrid(DD / 64, NROWS / 64);
    gemm_single<<<ggrid, 256>>>(ctx, wc, bc, out);
}

// round 13
// speedup vs baseline: 3.5265x; 1.3421x over previous
#include <cuda_runtime.h>
#include <cuda_fp16.h>
#include <cstdint>

#define BB 2
#define SS 2048
#define DD 256
#define HH 8
#define DH 32
#define NROWS (BB*SS)   // 4096

// Scratch (device globals: no allocation allowed)
__device__ float  g_q[NROWS*DD];
__device__ float  g_k[NROWS*DD];
__device__ float  g_v[NROWS*DD];
__device__ __half g_xh[NROWS*DD];    // x fp16
__device__ __half g_wh[3*DD*DD];     // Wq,Wk,Wv fp16
__device__ __half g_wch[DD*DD];      // Wfc@Wo fp16
__device__ __half g_qh[NROWS*DD];
__device__ __half g_kh[NROWS*DD];
__device__ __half g_vt[NROWS*DD];    // V fp16, transposed per (b,h): [(b*HH+h)*DH + c][t]
__device__ __half g_ctxh[NROWS*DD];  // attention output fp16
__device__ float2 g_sqq[NROWS*HH];   // q {tanh^2, cosh^2}, h-major: [h*NROWS + r]
__device__ float2 g_sqk[NROWS*HH];   // k likewise
__device__ float  g_bc[DD];

typedef unsigned long long u64;

// ---- f16 mma / cp.async helpers ----
__device__ __forceinline__ uint32_t h2(float lo, float hi){
    uint32_t r; asm("cvt.rn.f16x2.f32 %0, %1, %2;" : "=r"(r) : "f"(hi), "f"(lo)); return r;
}
__device__ __forceinline__ void mma_f16(float (&c)[4], const uint32_t (&a)[4], const uint32_t (&b)[2]){
    asm volatile("mma.sync.aligned.m16n8k16.row.col.f32.f16.f16.f32 "
        "{%0,%1,%2,%3}, {%4,%5,%6,%7}, {%8,%9}, {%0,%1,%2,%3};"
        : "+f"(c[0]), "+f"(c[1]), "+f"(c[2]), "+f"(c[3])
        : "r"(a[0]), "r"(a[1]), "r"(a[2]), "r"(a[3]), "r"(b[0]), "r"(b[1]));
}
__device__ __forceinline__ float ex2(float x){
    float r; asm("ex2.approx.f32 %0, %1;" : "=f"(r) : "f"(x)); return r;
}
__device__ __forceinline__ void cpa16(uint32_t dst, const void* src){
    asm volatile("cp.async.ca.shared.global [%0], [%1], 16;" :: "r"(dst), "l"(src));
}
#define CP_COMMIT() asm volatile("cp.async.commit_group;" ::: "memory")
#define CP_WAIT0()  asm volatile("cp.async.wait_group 0;" ::: "memory")

// ---------------------------------------------------------------------------
// fp32 -> fp16 converters
// ---------------------------------------------------------------------------
__global__ __launch_bounds__(256) void xconv_kernel(
    const float* __restrict__ src, __half* __restrict__ dst)
{
    int idx = (blockIdx.x * 256 + threadIdx.x) * 4;
    float4 v = *(const float4*)&src[idx];
    uint2 o; o.x = h2(v.x, v.y); o.y = h2(v.z, v.w);
    *(uint2*)&dst[idx] = o;
}

__global__ __launch_bounds__(256) void wconv_kernel(
    const float* __restrict__ Wq, const float* __restrict__ Wk,
    const float* __restrict__ Wv, __half* __restrict__ wh)
{
    const float* src = blockIdx.y == 0 ? Wq : (blockIdx.y == 1 ? Wk : Wv);
    int idx = (blockIdx.x * 256 + threadIdx.x) * 4;
    float4 v = *(const float4*)&src[idx];
    uint2 o; o.x = h2(v.x, v.y); o.y = h2(v.z, v.w);
    *(uint2*)&wh[blockIdx.y * DD * DD + idx] = o;
}

// ---------------------------------------------------------------------------
// fp16 tensor-core GEMM: C[m,n] = sum_k A[m,k]*B[n,k] + bias[n]  (fp32 accum)
// Block 128 thr = 4 warps; tile M=64 (warp m16), N=64 (8 n8), K chunks of 64.
// smem stride 72 halves => all fragment reads bank-conflict-free.
// ---------------------------------------------------------------------------
__device__ __forceinline__ void gemm16_body(
    const __half* __restrict__ A, const __half* __restrict__ B,
    const float* __restrict__ bias, float* __restrict__ C)
{
    __shared__ __align__(16) __half sA[64][72];
    __shared__ __align__(16) __half sB[64][72];

    const int tid = threadIdx.x;
    const int w   = tid >> 5;
    const int lane= tid & 31;
    const int g   = lane >> 2;
    const int t4  = lane & 3;
    const int m0  = blockIdx.y * 64;
    const int n0  = blockIdx.x * 64;

    float acc[8][4];
    #pragma unroll
    for (int nt = 0; nt < 8; nt++)
        #pragma unroll
        for (int r = 0; r < 4; r++) acc[nt][r] = 0.0f;

    for (int k0 = 0; k0 < DD; k0 += 64) {
        __syncthreads();
        #pragma unroll
        for (int i = 0; i < 4; i++) {
            int l = tid + i * 128;          // 0..511
            int row = l >> 3, j = l & 7;
            *(uint4*)&sA[row][j*8] = *(const uint4*)&A[(m0 + row) * DD + k0 + j*8];
            *(uint4*)&sB[row][j*8] = *(const uint4*)&B[(n0 + row) * DD + k0 + j*8];
        }
        __syncthreads();
        #pragma unroll
        for (int ks = 0; ks < 4; ks++) {
            uint32_t a[4];
            a[0] = *(const uint32_t*)&sA[w*16 + g    ][ks*16 + 2*t4];
            a[1] = *(const uint32_t*)&sA[w*16 + g + 8][ks*16 + 2*t4];
            a[2] = *(const uint32_t*)&sA[w*16 + g    ][ks*16 + 8 + 2*t4];
            a[3] = *(const uint32_t*)&sA[w*16 + g + 8][ks*16 + 8 + 2*t4];
            #pragma unroll
            for (int nt = 0; nt < 8; nt++) {
                uint32_t b[2];
                b[0] = *(const uint32_t*)&sB[nt*8 + g][ks*16 + 2*t4];
                b[1] = *(const uint32_t*)&sB[nt*8 + g][ks*16 + 8 + 2*t4];
                mma_f16(acc[nt], a, b);
            }
        }
    }

    #pragma unroll
    for (int nt = 0; nt < 8; nt++) {
        int c0 = n0 + nt*8 + 2*t4;
        float2 bb = *(const float2*)&bias[c0];
        int r0 = m0 + w*16 + g;
        float2 o0; o0.x = acc[nt][0] + bb.x; o0.y = acc[nt][1] + bb.y;
        float2 o1; o1.x = acc[nt][2] + bb.x; o1.y = acc[nt][3] + bb.y;
        *(float2*)&C[r0*DD + c0]       = o0;
        *(float2*)&C[(r0+8)*DD + c0]   = o1;
    }
}

__global__ __launch_bounds__(128) void gemm16_qkv(
    const __half* __restrict__ xh, const __half* __restrict__ wh,
    const float* __restrict__ bq, const float* __restrict__ bk,
    const float* __restrict__ bv, float* __restrict__ q,
    float* __restrict__ k, float* __restrict__ v)
{
    const __half* B = wh + blockIdx.z * DD * DD;
    const float* bias = blockIdx.z == 0 ? bq : (blockIdx.z == 1 ? bk : bv);
    float* C = blockIdx.z == 0 ? q : (blockIdx.z == 1 ? k : v);
    gemm16_body(xh, B, bias, C);
}

__global__ __launch_bounds__(128) void gemm16_one(
    const __half* __restrict__ A, const __half* __restrict__ B,
    const float* __restrict__ bias, float* __restrict__ C)
{
    gemm16_body(A, B, bias, C);
}

// ---------------------------------------------------------------------------
// Wcomb = Wfc @ Wo (emitted fp16), bcomb = Wfc @ bo + bfc (fp32)
// ---------------------------------------------------------------------------
__global__ __launch_bounds__(256) void wcomb_kernel(
    const float* __restrict__ Wfc, const float* __restrict__ Wo,
    __half* __restrict__ Wc)
{
    __shared__ float wf[DD];
    const int n = blockIdx.x;
    const int kx = threadIdx.x;
    wf[kx] = Wfc[n * DD + kx];
    __syncthreads();
    float a0 = 0.f, a1 = 0.f, a2 = 0.f, a3 = 0.f;
    #pragma unroll 4
    for (int j = 0; j < DD; j += 4) {
        a0 = fmaf(wf[j+0], Wo[(j+0) * DD + kx], a0);
        a1 = fmaf(wf[j+1], Wo[(j+1) * DD + kx], a1);
        a2 = fmaf(wf[j+2], Wo[(j+2) * DD + kx], a2);
        a3 = fmaf(wf[j+3], Wo[(j+3) * DD + kx], a3);
    }
    Wc[n * DD + kx] = __float2half((a0 + a1) + (a2 + a3));
}

__global__ __launch_bounds__(256) void bcomb_kernel(
    const float* __restrict__ Wfc, const float* __restrict__ bo,
    const float* __restrict__ bfc, float* __restrict__ bc)
{
    const int n = threadIdx.x;
    float acc = bfc[n];
    for (int j = 0; j < DD; j++) acc = fmaf(Wfc[n * DD + j], bo[j], acc);
    bc[n] = acc;
}

// ---------------------------------------------------------------------------
// expmap0 for q and k (blockIdx.y selects tensor). Emits fp16 mapped vectors
// + {tanh^2, cosh^2} in h-major layout [h*NROWS + row].
// ---------------------------------------------------------------------------
__global__ __launch_bounds__(256) void expmap_kernel(
    const float* __restrict__ q, const float* __restrict__ k,
    __half* __restrict__ qh, __half* __restrict__ kh,
    float2* __restrict__ sqq, float2* __restrict__ sqk)
{
    const float* p = blockIdx.y ? k : q;
    __half* p16    = blockIdx.y ? kh : qh;
    float2* so     = blockIdx.y ? sqk : sqq;
    const int row  = blockIdx.x;
    const int h    = threadIdx.x >> 5;
    const int lane = threadIdx.x & 31;
    const int idx  = row * DD + h * DH + lane;
    float v = p[idx];
    float s = v * v;
    #pragma unroll
    for (int o = 16; o; o >>= 1) s += __shfl_xor_sync(0xffffffffu, s, o);
    float n2  = fmaxf(s, 1e-12f);
    float nrm = sqrtf(n2);
    float t   = tanhf(nrm);
    p16[idx] = __float2half(v * (t / nrm));
    if (lane == 0) {
        float ch = coshf(nrm);
        so[h * NROWS + row] = make_float2(t * t, ch * ch);
    }
}

// ---------------------------------------------------------------------------
// V -> fp16 transposed per (b,h): vt[((b*HH+h)*DH + c)*SS + t]
// ---------------------------------------------------------------------------
__global__ __launch_bounds__(256) void vconv_kernel(
    const float* __restrict__ v, __half* __restrict__ vt)
{
    __shared__ float sv[64][33];
    const int b  = blockIdx.z, h = blockIdx.y, t0 = blockIdx.x * 64;
    const int tid = threadIdx.x;
    #pragma unroll
    for (int i = 0; i < 8; i++) {
        int l = tid + i*256;
        int row = l >> 5, c = l & 31;
        sv[row][c] = v[(b*SS + t0 + row)*DD + h*DH + c];
    }
    __syncthreads();
    const int c = tid >> 3, j = tid & 7;
    uint32_t o[4];
    #pragma unroll
    for (int r = 0; r < 4; r++)
        o[r] = h2(sv[j*8 + 2*r][c], sv[j*8 + 2*r + 1][c]);
    *(uint4*)&vt[((b*HH + h)*DH + c)*SS + t0 + j*8] = *(uint4*)o;
}

// ---------------------------------------------------------------------------
// Attention: fp16 mma for S = QK^T and O += P V, cp.async double-buffered.
//   u = cosh(dist) = 1 + (qq + kk - 2 qk) * (2 ch2_q ch2_k)
//   w = g^(-a), g = u + sqrt(u^2-1); for u >= 30, g ~= 2u (w-err <= 4.9e-5):
//   w = ex2(fma(lg2(min(u,UCLIP)), -a, -a)); 2*UCLIP = (1+T)/(1-T) exactly.
// Epilogue stores ctx as fp16 (consumed by the fp16 output GEMM).
// ---------------------------------------------------------------------------
#define KT 64
#define SC_EXP 0.17677669529663689f
#define NEG_A  (-0.17677669529663689f)
#define UCLIP  99999.5f
#define WCLIP  0.11558618f
#define UAPPROX 30.0f

__global__ __launch_bounds__(128) void attn_kernel(
    const __half* __restrict__ qh16, const __half* __restrict__ kh16,
    const __half* __restrict__ vt, const float2* __restrict__ cq,
    const float2* __restrict__ ckc, __half* __restrict__ ctxh)
{
    __shared__ __align__(16) __half sKh[2][KT][40];
    __shared__ __align__(16) __half sVt[2][DH][72];
    __shared__ __align__(16) float2 sKC[2][KT];

    const int b   = blockIdx.z;
    const int h   = blockIdx.y;
    const int q0  = blockIdx.x * 128;
    const int tid = threadIdx.x;
    const int w   = tid >> 5;
    const int lane= tid & 31;
    const int g   = lane >> 2;
    const int t4  = lane & 3;
    const int wrow = w * 32;

    const __half* vtb = vt + (size_t)((b*HH + h)*DH) * SS;
    const float2* kcb = ckc + h*NROWS + b*SS;

    const uint32_t sKh_a = (uint32_t)__cvta_generic_to_shared(&sKh[0][0][0]);
    const uint32_t sVt_a = (uint32_t)__cvta_generic_to_shared(&sVt[0][0][0]);
    const uint32_t sKC_a = (uint32_t)__cvta_generic_to_shared(&sKC[0][0]);

    // per-thread row constants (rows wrow + m*16 + rh*8 + g)
    float qqr[4], fr2[4];
    #pragma unroll
    for (int m = 0; m < 2; m++)
        #pragma unroll
        for (int rh = 0; rh < 2; rh++) {
            int r = b*SS + q0 + wrow + m*16 + rh*8 + g;
            float2 c = cq[h*NROWS + r];
            qqr[m*2+rh] = c.x;
            fr2[m*2+rh] = 2.0f * c.y;
        }

    // Q fragments: f16 m16n8k16 A layout, 2 k-chunks of 16 dims.
    uint32_t qf[2][2][4];
    #pragma unroll
    for (int m = 0; m < 2; m++)
        #pragma unroll
        for (int ks = 0; ks < 2; ks++) {
            int r0 = b*SS + q0 + wrow + m*16 + g;
            int c0 = h*DH + ks*16 + 2*t4;
            qf[m][ks][0] = *(const uint32_t*)&qh16[r0*DD + c0];
            qf[m][ks][1] = *(const uint32_t*)&qh16[(r0+8)*DD + c0];
            qf[m][ks][2] = *(const uint32_t*)&qh16[r0*DD + c0 + 8];
            qf[m][ks][3] = *(const uint32_t*)&qh16[(r0+8)*DD + c0 + 8];
        }

    float O[2][4][4];
    #pragma unroll
    for (int m = 0; m < 2; m++)
        #pragma unroll
        for (int nt = 0; nt < 4; nt++)
            #pragma unroll
            for (int r = 0; r < 4; r++) O[m][nt][r] = 0.0f;
    float lacc[4] = {0.f, 0.f, 0.f, 0.f};

    // tile loader (cp.async): K 256x16B, Vt 256x16B, KC 32x16B
    auto load_tile = [&](int t0, int s) {
        #pragma unroll
        for (int i = 0; i < 2; i++) {
            int l = tid + i*128;
            int row = l >> 2, j = l & 3;
            cpa16(sKh_a + ((s*KT + row)*40 + j*8)*2,
                  &kh16[(b*SS + t0 + row)*DD + h*DH + j*8]);
        }
        #pragma unroll
        for (int i = 0; i < 2; i++) {
            int l = tid + i*128;
            int c = l >> 3, j = l & 7;
            cpa16(sVt_a + ((s*DH + c)*72 + j*8)*2, &vtb[c*SS + t0 + j*8]);
        }
        if (tid < 32) cpa16(sKC_a + (s*KT + tid*2)*8, &kcb[t0 + tid*2]);
    };

    load_tile(0, 0);
    CP_COMMIT();

    #pragma unroll 1
    for (int it = 0; it < SS/KT; it++) {
        const int s = it & 1;
        CP_WAIT0();
        __syncthreads();
        if (it + 1 < SS/KT) {
            load_tile((it+1)*KT, s ^ 1);
            CP_COMMIT();
        }

        #pragma unroll 1
        for (int half = 0; half < 2; half++) {
            // ---- S = Q K^T for keys [half*32, half*32+32) ----
            float S[2][4][4];
            #pragma unroll
            for (int m = 0; m < 2; m++)
                #pragma unroll
                for (int nt = 0; nt < 4; nt++)
                    #pragma unroll
                    for (int r = 0; r < 4; r++) S[m][nt][r] = 0.0f;

            #pragma unroll
            for (int nt = 0; nt < 4; nt++) {
                int kr = half*32 + nt*8 + g;
                #pragma unroll
                for (int ks = 0; ks < 2; ks++) {
                    uint32_t bb[2];
                    bb[0] = *(const uint32_t*)&sKh[s][kr][ks*16 + 2*t4];
                    bb[1] = *(const uint32_t*)&sKh[s][kr][ks*16 + 8 + 2*t4];
                    mma_f16(S[0][nt], qf[0][ks], bb);
                    mma_f16(S[1][nt], qf[1][ks], bb);
                }
            }

            // ---- qk -> u = cosh(dist), vote on rare exact path ----
            float2 kcr[8];
            #pragma unroll
            for (int nt = 0; nt < 4; nt++)
                #pragma unroll
                for (int rb = 0; rb < 2; rb++)
                    kcr[nt*2+rb] = sKC[s][half*32 + nt*8 + 2*t4 + rb];

            bool need = false;
            #pragma unroll
            for (int m = 0; m < 2; m++)
                #pragma unroll
                for (int nt = 0; nt < 4; nt++)
                    #pragma unroll
                    for (int r = 0; r < 4; r++) {
                        int ci   = nt*2 + (r & 1);
                        int ridx = m*2 + (r >> 1);
                        float nm = fmaf(-2.0f, S[m][nt][r], qqr[ridx] + kcr[ci].x);
                        float u  = fmaf(nm, fr2[ridx] * kcr[ci].y, 1.0f);
                        need |= (u < UAPPROX);
                        S[m][nt][r] = u;
                    }

            if (__any_sync(0xffffffffu, need)) {
                #pragma unroll
                for (int m = 0; m < 2; m++)
                    #pragma unroll
                    for (int nt = 0; nt < 4; nt++)
                        #pragma unroll
                        for (int r = 0; r < 4; r++) {
                            int ridx = m*2 + (r >> 1);
                            float u = S[m][nt][r];
                            float w_ = WCLIP;
                            if (u < UCLIP) {
                                float t = fmaf(u, u, -1.0f);
                                t = fmaxf(t, 0.0f);
                                float gg = u + t * rsqrtf(fmaxf(t, 1e-30f));
                                gg = fmaxf(gg, 1.0f);
                                w_ = ex2(-SC_EXP * __log2f(gg));
                            }
                            lacc[ridx] += w_;
                            S[m][nt][r] = w_;
                        }
            } else {
                #pragma unroll
                for (int m = 0; m < 2; m++)
                    #pragma unroll
                    for (int nt = 0; nt < 4; nt++)
                        #pragma unroll
                        for (int r = 0; r < 4; r++) {
                            int ridx = m*2 + (r >> 1);
                            float um = fminf(S[m][nt][r], UCLIP);
                            float w_ = ex2(fmaf(__log2f(um), NEG_A, NEG_A));
                            lacc[ridx] += w_;
                            S[m][nt][r] = w_;
                        }
            }

            // ---- pack P into f16 A-fragments (register-only) ----
            uint32_t pa[2][2][4];
            #pragma unroll
            for (int m = 0; m < 2; m++)
                #pragma unroll
                for (int kc2 = 0; kc2 < 2; kc2++) {
                    int nt0 = 2*kc2, nt1 = 2*kc2 + 1;
                    pa[m][kc2][0] = h2(S[m][nt0][0], S[m][nt0][1]);
                    pa[m][kc2][1] = h2(S[m][nt0][2], S[m][nt0][3]);
                    pa[m][kc2][2] = h2(S[m][nt1][0], S[m][nt1][1]);
                    pa[m][kc2][3] = h2(S[m][nt1][2], S[m][nt1][3]);
                }

            // ---- O += P V  (B-frags: direct LDS.32 from transposed fp16 V) ----
            #pragma unroll
            for (int kc2 = 0; kc2 < 2; kc2++) {
                int kb = half*32 + kc2*16;
                #pragma unroll
                for (int nt = 0; nt < 4; nt++) {
                    int col = nt*8 + g;
                    uint32_t bb[2];
                    bb[0] = *(const uint32_t*)&sVt[s][col][kb + 2*t4];
                    bb[1] = *(const uint32_t*)&sVt[s][col][kb + 8 + 2*t4];
                    mma_f16(O[0][nt], pa[0][kc2], bb);
                    mma_f16(O[1][nt], pa[1][kc2], bb);
                }
            }
        }
        __syncthreads();
    }

    // ---- epilogue: reduce l over quad, normalize, store fp16 ctx ----
    #pragma unroll
    for (int i = 0; i < 4; i++) {
        lacc[i] += __shfl_xor_sync(0xffffffffu, lacc[i], 1);
        lacc[i] += __shfl_xor_sync(0xffffffffu, lacc[i], 2);
        lacc[i] = __fdividef(1.0f, lacc[i]);
    }
    #pragma unroll
    for (int m = 0; m < 2; m++)
        #pragma unroll
        for (int rh = 0; rh < 2; rh++) {
            int grow = b*SS + q0 + wrow + m*16 + rh*8 + g;
            float rl = lacc[m*2 + rh];
            #pragma unroll
            for (int nt = 0; nt < 4; nt++) {
                uint32_t o = h2(O[m][nt][rh*2 + 0] * rl, O[m][nt][rh*2 + 1] * rl);
                *(uint32_t*)&ctxh[grow*DD + h*DH + nt*8 + 2*t4] = o;
            }
        }
}

// ---------------------------------------------------------------------------

extern "C" void kernel_launch(void* const* d_in, const int* in_sizes, int n_in,
                              void* d_out, int out_size)
{
    const float* x   = (const float*)d_in[0];
    const float* Wq  = (const float*)d_in[1];
    const float* bq  = (const float*)d_in[2];
    const float* Wk  = (const float*)d_in[3];
    const float* bk  = (const float*)d_in[4];
    const float* Wv  = (const float*)d_in[5];
    const float* bv  = (const float*)d_in[6];
    const float* Wo  = (const float*)d_in[7];
    const float* bo  = (const float*)d_in[8];
    const float* Wfc = (const float*)d_in[9];
    const float* bfc = (const float*)d_in[10];
    float* out = (float*)d_out;

    float *q, *k, *v, *bc;
    __half *xh, *wh, *wch, *qh, *kh, *vt, *ctxh;
    float2 *sqq, *sqk;
    cudaGetSymbolAddress((void**)&q,    g_q);
    cudaGetSymbolAddress((void**)&k,    g_k);
    cudaGetSymbolAddress((void**)&v,    g_v);
    cudaGetSymbolAddress((void**)&xh,   g_xh);
    cudaGetSymbolAddress((void**)&wh,   g_wh);
    cudaGetSymbolAddress((void**)&wch,  g_wch);
    cudaGetSymbolAddress((void**)&qh,   g_qh);
    cudaGetSymbolAddress((void**)&kh,   g_kh);
    cudaGetSymbolAddress((void**)&vt,   g_vt);
    cudaGetSymbolAddress((void**)&ctxh, g_ctxh);
    cudaGetSymbolAddress((void**)&sqq,  g_sqq);
    cudaGetSymbolAddress((void**)&sqk,  g_sqk);
    cudaGetSymbolAddress((void**)&bc,   g_bc);

    // Combined output weights (fp16) + bias
    wcomb_kernel<<<DD, DD>>>(Wfc, Wo, wch);
    bcomb_kernel<<<1, DD>>>(Wfc, bo, bfc, bc);

    // fp16 conversions of x and Wq/Wk/Wv
    xconv_kernel<<<NROWS*DD/1024, 256>>>(x, xh);
    dim3 wgrid(DD*DD/1024, 3);
    wconv_kernel<<<wgrid, 256>>>(Wq, Wk, Wv, wh);

    // Q/K/V projections: fp16 tensor-core GEMM
    dim3 qkvgrid(DD/64, NROWS/64, 3);
    gemm16_qkv<<<qkvgrid, 128>>>(xh, wh, bq, bk, bv, q, k, v);

    // expmap0 (q,k -> fp16 + constants) and V transpose/convert
    dim3 egrid(NROWS, 2);
    expmap_kernel<<<egrid, 256>>>(q, k, qh, kh, sqq, sqk);
    dim3 vgrid(SS/64, HH, BB);
    vconv_kernel<<<vgrid, 256>>>(v, vt);

    // attention (fp16 mma, cp.async double-buffered) -> fp16 ctx
    dim3 agrid(SS/128, HH, BB);
    attn_kernel<<<agrid, 128>>>(qh, kh, vt, sqq, sqk, ctxh);

    // fused output projection + fc: fp16 tensor-core GEMM
    dim3 ogrid(DD/64, NROWS/64);
    gemm16_one<<<ogrid, 128>>>(ctxh, wch, bc, out);
}

// round 14
// speedup vs baseline: 3.6218x; 1.0270x over previous
#include <cuda_runtime.h>
#include <cuda_fp16.h>
#include <cstdint>

#define BB 2
#define SS 2048
#define DD 256
#define HH 8
#define DH 32
#define NROWS (BB*SS)   // 4096

// Scratch (device globals: no allocation allowed)
__device__ float  g_q[NROWS*DD];
__device__ float  g_k[NROWS*DD];
__device__ __half g_xh[NROWS*DD];    // x fp16
__device__ __half g_wh[3*DD*DD];     // Wq,Wk,Wv fp16
__device__ __half g_wch[DD*DD];      // Wfc@Wo fp16
__device__ __half g_qh[NROWS*DD];
__device__ __half g_kh[NROWS*DD];
__device__ __half g_vt[NROWS*DD];    // V fp16, transposed per (b,h): [(b*HH+h)*DH + c][t]
__device__ __half g_ctxh[NROWS*DD];  // attention output fp16
__device__ float2 g_sqq[NROWS*HH];   // q {tanh^2, cosh^2}, h-major: [h*NROWS + r]
__device__ float2 g_sqk[NROWS*HH];   // k likewise
__device__ float  g_bc[DD];

typedef unsigned long long u64;

// ---- f16 mma / cp.async helpers ----
__device__ __forceinline__ uint32_t h2(float lo, float hi){
    uint32_t r; asm("cvt.rn.f16x2.f32 %0, %1, %2;" : "=r"(r) : "f"(hi), "f"(lo)); return r;
}
__device__ __forceinline__ void mma_f16(float (&c)[4], const uint32_t (&a)[4], const uint32_t (&b)[2]){
    asm volatile("mma.sync.aligned.m16n8k16.row.col.f32.f16.f16.f32 "
        "{%0,%1,%2,%3}, {%4,%5,%6,%7}, {%8,%9}, {%0,%1,%2,%3};"
        : "+f"(c[0]), "+f"(c[1]), "+f"(c[2]), "+f"(c[3])
        : "r"(a[0]), "r"(a[1]), "r"(a[2]), "r"(a[3]), "r"(b[0]), "r"(b[1]));
}
__device__ __forceinline__ float ex2(float x){
    float r; asm("ex2.approx.f32 %0, %1;" : "=f"(r) : "f"(x)); return r;
}
__device__ __forceinline__ void cpa16(uint32_t dst, const void* src){
    asm volatile("cp.async.ca.shared.global [%0], [%1], 16;" :: "r"(dst), "l"(src));
}
#define CP_COMMIT() asm volatile("cp.async.commit_group;" ::: "memory")
#define CP_WAIT0()  asm volatile("cp.async.wait_group 0;" ::: "memory")

// ---------------------------------------------------------------------------
// Combined fp32 -> fp16 converter: x (1024 blocks) + Wq/Wk/Wv (64 each)
// ---------------------------------------------------------------------------
__global__ __launch_bounds__(256) void conv_kernel(
    const float* __restrict__ x, const float* __restrict__ Wq,
    const float* __restrict__ Wk, const float* __restrict__ Wv,
    __half* __restrict__ xh, __half* __restrict__ wh)
{
    int bid = blockIdx.x;
    const float* src; __half* dst; int base;
    if (bid < 1024) { src = x; dst = xh; base = bid * 1024; }
    else {
        int wb = bid - 1024;
        int which = wb >> 6;
        src = which == 0 ? Wq : (which == 1 ? Wk : Wv);
        dst = wh + which * DD * DD;
        base = (wb & 63) * 1024;
    }
    int idx = base + threadIdx.x * 4;
    float4 v = *(const float4*)&src[idx];
    uint2 o; o.x = h2(v.x, v.y); o.y = h2(v.z, v.w);
    *(uint2*)&dst[idx] = o;
}

// ---------------------------------------------------------------------------
// fp16 tensor-core GEMM mainloop (fp32 accum). Tile M=64, N=64, K steps 64.
// ---------------------------------------------------------------------------
__device__ __forceinline__ void gemm16_mainloop(
    const __half* __restrict__ A, const __half* __restrict__ B,
    float (&acc)[8][4], int m0, int n0,
    __half (*sA)[72], __half (*sB)[72])
{
    const int tid = threadIdx.x;
    const int w   = tid >> 5;
    const int lane= tid & 31;
    const int g   = lane >> 2;
    const int t4  = lane & 3;

    for (int k0 = 0; k0 < DD; k0 += 64) {
        __syncthreads();
        #pragma unroll
        for (int i = 0; i < 4; i++) {
            int l = tid + i * 128;
            int row = l >> 3, j = l & 7;
            *(uint4*)&sA[row][j*8] = *(const uint4*)&A[(m0 + row) * DD + k0 + j*8];
            *(uint4*)&sB[row][j*8] = *(const uint4*)&B[(n0 + row) * DD + k0 + j*8];
        }
        __syncthreads();
        #pragma unroll
        for (int ks = 0; ks < 4; ks++) {
            uint32_t a[4];
            a[0] = *(const uint32_t*)&sA[w*16 + g    ][ks*16 + 2*t4];
            a[1] = *(const uint32_t*)&sA[w*16 + g + 8][ks*16 + 2*t4];
            a[2] = *(const uint32_t*)&sA[w*16 + g    ][ks*16 + 8 + 2*t4];
            a[3] = *(const uint32_t*)&sA[w*16 + g + 8][ks*16 + 8 + 2*t4];
            #pragma unroll
            for (int nt = 0; nt < 8; nt++) {
                uint32_t b[2];
                b[0] = *(const uint32_t*)&sB[nt*8 + g][ks*16 + 2*t4];
                b[1] = *(const uint32_t*)&sB[nt*8 + g][ks*16 + 8 + 2*t4];
                mma_f16(acc[nt], a, b);
            }
        }
    }
}

// QKV: z=0,1 write fp32 q/k; z=2 writes transposed fp16 vt via smem staging.
__global__ __launch_bounds__(128) void gemm16_qkv(
    const __half* __restrict__ xh, const __half* __restrict__ wh,
    const float* __restrict__ bq, const float* __restrict__ bk,
    const float* __restrict__ bv, float* __restrict__ q,
    float* __restrict__ k, __half* __restrict__ vt)
{
    __shared__ __align__(16) __half sA[64][72];
    __shared__ __align__(16) __half sB[64][72];

    const int z = blockIdx.z;
    const __half* B = wh + z * DD * DD;
    const float* bias = z == 0 ? bq : (z == 1 ? bk : bv);
    const int m0 = blockIdx.y * 64;
    const int n0 = blockIdx.x * 64;
    const int tid = threadIdx.x;
    const int w   = tid >> 5;
    const int lane= tid & 31;
    const int g   = lane >> 2;
    const int t4  = lane & 3;

    float acc[8][4];
    #pragma unroll
    for (int nt = 0; nt < 8; nt++)
        #pragma unroll
        for (int r = 0; r < 4; r++) acc[nt][r] = 0.0f;

    gemm16_mainloop(xh, B, acc, m0, n0, sA, sB);

    if (z < 2) {
        float* C = z == 0 ? q : k;
        #pragma unroll
        for (int nt = 0; nt < 8; nt++) {
            int c0 = n0 + nt*8 + 2*t4;
            float2 bb = *(const float2*)&bias[c0];
            int r0 = m0 + w*16 + g;
            float2 o0; o0.x = acc[nt][0] + bb.x; o0.y = acc[nt][1] + bb.y;
            float2 o1; o1.x = acc[nt][2] + bb.x; o1.y = acc[nt][3] + bb.y;
            *(float2*)&C[r0*DD + c0]     = o0;
            *(float2*)&C[(r0+8)*DD + c0] = o1;
        }
    } else {
        // V: stage fp16 transpose in sA, then coalesced store to vt
        __syncthreads();
        __half (*sT)[72] = sA;
        #pragma unroll
        for (int nt = 0; nt < 8; nt++) {
            int cl = nt*8 + 2*t4;
            float2 bb = *(const float2*)&bias[n0 + cl];
            sT[cl  ][w*16 + g]     = __float2half(acc[nt][0] + bb.x);
            sT[cl+1][w*16 + g]     = __float2half(acc[nt][1] + bb.y);
            sT[cl  ][w*16 + g + 8] = __float2half(acc[nt][2] + bb.x);
            sT[cl+1][w*16 + g + 8] = __float2half(acc[nt][3] + bb.y);
        }
        __syncthreads();
        const int b  = (m0 >= SS) ? 1 : 0;
        const int t0 = m0 & (SS - 1);
        #pragma unroll
        for (int i = 0; i < 4; i++) {
            int l = tid + i*128;
            int row = l >> 3, jj = l & 7;
            *(uint4*)&vt[(size_t)(b*HH*DH + n0 + row)*SS + t0 + jj*8] =
                *(uint4*)&sT[row][jj*8];
        }
    }
}

__global__ __launch_bounds__(128) void gemm16_one(
    const __half* __restrict__ A, const __half* __restrict__ B,
    const float* __restrict__ bias, float* __restrict__ C)
{
    __shared__ __align__(16) __half sA[64][72];
    __shared__ __align__(16) __half sB[64][72];
    const int m0 = blockIdx.y * 64;
    const int n0 = blockIdx.x * 64;
    const int tid = threadIdx.x;
    const int w   = tid >> 5;
    const int lane= tid & 31;
    const int g   = lane >> 2;
    const int t4  = lane & 3;

    float acc[8][4];
    #pragma unroll
    for (int nt = 0; nt < 8; nt++)
        #pragma unroll
        for (int r = 0; r < 4; r++) acc[nt][r] = 0.0f;

    gemm16_mainloop(A, B, acc, m0, n0, sA, sB);

    #pragma unroll
    for (int nt = 0; nt < 8; nt++) {
        int c0 = n0 + nt*8 + 2*t4;
        float2 bb = *(const float2*)&bias[c0];
        int r0 = m0 + w*16 + g;
        float2 o0; o0.x = acc[nt][0] + bb.x; o0.y = acc[nt][1] + bb.y;
        float2 o1; o1.x = acc[nt][2] + bb.x; o1.y = acc[nt][3] + bb.y;
        *(float2*)&C[r0*DD + c0]     = o0;
        *(float2*)&C[(r0+8)*DD + c0] = o1;
    }
}

// ---------------------------------------------------------------------------
// Wcomb = Wfc @ Wo (fp16), bcomb = Wfc @ bo + bfc (fp32)
// ---------------------------------------------------------------------------
__global__ __launch_bounds__(256) void wcomb_kernel(
    const float* __restrict__ Wfc, const float* __restrict__ Wo,
    __half* __restrict__ Wc)
{
    __shared__ float wf[DD];
    const int n = blockIdx.x;
    const int kx = threadIdx.x;
    wf[kx] = Wfc[n * DD + kx];
    __syncthreads();
    float a0 = 0.f, a1 = 0.f, a2 = 0.f, a3 = 0.f;
    #pragma unroll 4
    for (int j = 0; j < DD; j += 4) {
        a0 = fmaf(wf[j+0], Wo[(j+0) * DD + kx], a0);
        a1 = fmaf(wf[j+1], Wo[(j+1) * DD + kx], a1);
        a2 = fmaf(wf[j+2], Wo[(j+2) * DD + kx], a2);
        a3 = fmaf(wf[j+3], Wo[(j+3) * DD + kx], a3);
    }
    Wc[n * DD + kx] = __float2half((a0 + a1) + (a2 + a3));
}

__global__ __launch_bounds__(256) void bcomb_kernel(
    const float* __restrict__ Wfc, const float* __restrict__ bo,
    const float* __restrict__ bfc, float* __restrict__ bc)
{
    const int n = threadIdx.x;
    float acc = bfc[n];
    for (int j = 0; j < DD; j++) acc = fmaf(Wfc[n * DD + j], bo[j], acc);
    bc[n] = acc;
}

// ---------------------------------------------------------------------------
// expmap0 for q and k (blockIdx.y selects tensor). Fast-math:
//   t = tanh(n) = 1 - 2/(e^{2n}+1);  cosh(n) = (s + 1/s)/2, s = sqrt(e^{2n}).
// Emits fp16 mapped vectors + {tanh^2, cosh^2} h-major [h*NROWS + row].
// ---------------------------------------------------------------------------
__global__ __launch_bounds__(256) void expmap_kernel(
    const float* __restrict__ q, const float* __restrict__ k,
    __half* __restrict__ qh, __half* __restrict__ kh,
    float2* __restrict__ sqq, float2* __restrict__ sqk)
{
    const float* p = blockIdx.y ? k : q;
    __half* p16    = blockIdx.y ? kh : qh;
    float2* so     = blockIdx.y ? sqk : sqq;
    const int row  = blockIdx.x;
    const int h    = threadIdx.x >> 5;
    const int lane = threadIdx.x & 31;
    const int idx  = row * DD + h * DH + lane;
    float v = p[idx];
    float s = v * v;
    #pragma unroll
    for (int o = 16; o; o >>= 1) s += __shfl_xor_sync(0xffffffffu, s, o);
    float n2   = fmaxf(s, 1e-12f);
    float rinv = rsqrtf(n2);
    float nrm  = n2 * rinv;                         // sqrt(n2)
    float e2n  = ex2(nrm * 2.8853900817779268f);    // e^{2 nrm}
    float t    = 1.0f - __fdividef(2.0f, e2n + 1.0f);
    p16[idx] = __float2half(v * t * rinv);
    if (lane == 0) {
        float sq = sqrtf(e2n);                      // e^{nrm}
        float ch = 0.5f * (sq + __fdividef(1.0f, sq));
        so[h * NROWS + row] = make_float2(t * t, ch * ch);
    }
}

// ---------------------------------------------------------------------------
// Attention: fp16 mma for S = QK^T and O += P V, cp.async double-buffered.
//   u = cosh(dist) = 1 + (qq + kk - 2 qk) * (2 ch2_q ch2_k)
//   w = g^(-a), g = u + sqrt(u^2-1); for u >= 30, g ~= 2u (w-err <= 4.9e-5):
//   w = ex2(fma(lg2(min(u,UCLIP)), -a, -a)); 2*UCLIP = (1+T)/(1-T) exactly.
// Epilogue stores ctx as fp16 (consumed by the fp16 output GEMM).
// ---------------------------------------------------------------------------
#define KT 64
#define SC_EXP 0.17677669529663689f
#define NEG_A  (-0.17677669529663689f)
#define UCLIP  99999.5f
#define WCLIP  0.11558618f
#define UAPPROX 30.0f

__global__ __launch_bounds__(128) void attn_kernel(
    const __half* __restrict__ qh16, const __half* __restrict__ kh16,
    const __half* __restrict__ vt, const float2* __restrict__ cq,
    const float2* __restrict__ ckc, __half* __restrict__ ctxh)
{
    __shared__ __align__(16) __half sKh[2][KT][40];
    __shared__ __align__(16) __half sVt[2][DH][72];
    __shared__ __align__(16) float2 sKC[2][KT];

    const int b   = blockIdx.z;
    const int h   = blockIdx.y;
    const int q0  = blockIdx.x * 128;
    const int tid = threadIdx.x;
    const int w   = tid >> 5;
    const int lane= tid & 31;
    const int g   = lane >> 2;
    const int t4  = lane & 3;
    const int wrow = w * 32;

    const __half* vtb = vt + (size_t)((b*HH + h)*DH) * SS;
    const float2* kcb = ckc + h*NROWS + b*SS;

    const uint32_t sKh_a = (uint32_t)__cvta_generic_to_shared(&sKh[0][0][0]);
    const uint32_t sVt_a = (uint32_t)__cvta_generic_to_shared(&sVt[0][0][0]);
    const uint32_t sKC_a = (uint32_t)__cvta_generic_to_shared(&sKC[0][0]);

    float qqr[4], fr2[4];
    #pragma unroll
    for (int m = 0; m < 2; m++)
        #pragma unroll
        for (int rh = 0; rh < 2; rh++) {
            int r = b*SS + q0 + wrow + m*16 + rh*8 + g;
            float2 c = cq[h*NROWS + r];
            qqr[m*2+rh] = c.x;
            fr2[m*2+rh] = 2.0f * c.y;
        }

    uint32_t qf[2][2][4];
    #pragma unroll
    for (int m = 0; m < 2; m++)
        #pragma unroll
        for (int ks = 0; ks < 2; ks++) {
            int r0 = b*SS + q0 + wrow + m*16 + g;
            int c0 = h*DH + ks*16 + 2*t4;
            qf[m][ks][0] = *(const uint32_t*)&qh16[r0*DD + c0];
            qf[m][ks][1] = *(const uint32_t*)&qh16[(r0+8)*DD + c0];
            qf[m][ks][2] = *(const uint32_t*)&qh16[r0*DD + c0 + 8];
            qf[m][ks][3] = *(const uint32_t*)&qh16[(r0+8)*DD + c0 + 8];
        }

    float O[2][4][4];
    #pragma unroll
    for (int m = 0; m < 2; m++)
        #pragma unroll
        for (int nt = 0; nt < 4; nt++)
            #pragma unroll
            for (int r = 0; r < 4; r++) O[m][nt][r] = 0.0f;
    float lacc[4] = {0.f, 0.f, 0.f, 0.f};

    auto load_tile = [&](int t0, int s) {
        #pragma unroll
        for (int i = 0; i < 2; i++) {
            int l = tid + i*128;
            int row = l >> 2, j = l & 3;
            cpa16(sKh_a + ((s*KT + row)*40 + j*8)*2,
                  &kh16[(b*SS + t0 + row)*DD + h*DH + j*8]);
        }
        #pragma unroll
        for (int i = 0; i < 2; i++) {
            int l = tid + i*128;
            int c = l >> 3, j = l & 7;
            cpa16(sVt_a + ((s*DH + c)*72 + j*8)*2, &vtb[c*SS + t0 + j*8]);
        }
        if (tid < 32) cpa16(sKC_a + (s*KT + tid*2)*8, &kcb[t0 + tid*2]);
    };

    load_tile(0, 0);
    CP_COMMIT();

    #pragma unroll 1
    for (int it = 0; it < SS/KT; it++) {
        const int s = it & 1;
        CP_WAIT0();
        __syncthreads();
        if (it + 1 < SS/KT) {
            load_tile((it+1)*KT, s ^ 1);
            CP_COMMIT();
        }

        #pragma unroll 1
        for (int half = 0; half < 2; half++) {
            float S[2][4][4];
            #pragma unroll
            for (int m = 0; m < 2; m++)
                #pragma unroll
                for (int nt = 0; nt < 4; nt++)
                    #pragma unroll
                    for (int r = 0; r < 4; r++) S[m][nt][r] = 0.0f;

            #pragma unroll
            for (int nt = 0; nt < 4; nt++) {
                int kr = half*32 + nt*8 + g;
                #pragma unroll
                for (int ks = 0; ks < 2; ks++) {
                    uint32_t bb[2];
                    bb[0] = *(const uint32_t*)&sKh[s][kr][ks*16 + 2*t4];
                    bb[1] = *(const uint32_t*)&sKh[s][kr][ks*16 + 8 + 2*t4];
                    mma_f16(S[0][nt], qf[0][ks], bb);
                    mma_f16(S[1][nt], qf[1][ks], bb);
                }
            }

            float2 kcr[8];
            #pragma unroll
            for (int nt = 0; nt < 4; nt++)
                #pragma unroll
                for (int rb = 0; rb < 2; rb++)
                    kcr[nt*2+rb] = sKC[s][half*32 + nt*8 + 2*t4 + rb];

            bool need = false;
            #pragma unroll
            for (int m = 0; m < 2; m++)
                #pragma unroll
                for (int nt = 0; nt < 4; nt++)
                    #pragma unroll
                    for (int r = 0; r < 4; r++) {
                        int ci   = nt*2 + (r & 1);
                        int ridx = m*2 + (r >> 1);
                        float nm = fmaf(-2.0f, S[m][nt][r], qqr[ridx] + kcr[ci].x);
                        float u  = fmaf(nm, fr2[ridx] * kcr[ci].y, 1.0f);
                        need |= (u < UAPPROX);
                        S[m][nt][r] = u;
                    }

            if (__any_sync(0xffffffffu, need)) {
                #pragma unroll
                for (int m = 0; m < 2; m++)
                    #pragma unroll
                    for (int nt = 0; nt < 4; nt++)
                        #pragma unroll
                        for (int r = 0; r < 4; r++) {
                            int ridx = m*2 + (r >> 1);
                            float u = S[m][nt][r];
                            float w_ = WCLIP;
                            if (u < UCLIP) {
                                float t = fmaf(u, u, -1.0f);
                                t = fmaxf(t, 0.0f);
                                float gg = u + t * rsqrtf(fmaxf(t, 1e-30f));
                                gg = fmaxf(gg, 1.0f);
                                w_ = ex2(-SC_EXP * __log2f(gg));
                            }
                            lacc[ridx] += w_;
                            S[m][nt][r] = w_;
                        }
            } else {
                #pragma unroll
                for (int m = 0; m < 2; m++)
                    #pragma unroll
                    for (int nt = 0; nt < 4; nt++)
                        #pragma unroll
                        for (int r = 0; r < 4; r++) {
                            int ridx = m*2 + (r >> 1);
                            float um = fminf(S[m][nt][r], UCLIP);
                            float w_ = ex2(fmaf(__log2f(um), NEG_A, NEG_A));
                            lacc[ridx] += w_;
                            S[m][nt][r] = w_;
                        }
            }

            uint32_t pa[2][2][4];
            #pragma unroll
            for (int m = 0; m < 2; m++)
                #pragma unroll
                for (int kc2 = 0; kc2 < 2; kc2++) {
                    int nt0 = 2*kc2, nt1 = 2*kc2 + 1;
                    pa[m][kc2][0] = h2(S[m][nt0][0], S[m][nt0][1]);
                    pa[m][kc2][1] = h2(S[m][nt0][2], S[m][nt0][3]);
                    pa[m][kc2][2] = h2(S[m][nt1][0], S[m][nt1][1]);
                    pa[m][kc2][3] = h2(S[m][nt1][2], S[m][nt1][3]);
                }

            #pragma unroll
            for (int kc2 = 0; kc2 < 2; kc2++) {
                int kb = half*32 + kc2*16;
                #pragma unroll
                for (int nt = 0; nt < 4; nt++) {
                    int col = nt*8 + g;
                    uint32_t bb[2];
                    bb[0] = *(const uint32_t*)&sVt[s][col][kb + 2*t4];
                    bb[1] = *(const uint32_t*)&sVt[s][col][kb + 8 + 2*t4];
                    mma_f16(O[0][nt], pa[0][kc2], bb);
                    mma_f16(O[1][nt], pa[1][kc2], bb);
                }
            }
        }
        __syncthreads();
    }

    #pragma unroll
    for (int i = 0; i < 4; i++) {
        lacc[i] += __shfl_xor_sync(0xffffffffu, lacc[i], 1);
        lacc[i] += __shfl_xor_sync(0xffffffffu, lacc[i], 2);
        lacc[i] = __fdividef(1.0f, lacc[i]);
    }
    #pragma unroll
    for (int m = 0; m < 2; m++)
        #pragma unroll
        for (int rh = 0; rh < 2; rh++) {
            int grow = b*SS + q0 + wrow + m*16 + rh*8 + g;
            float rl = lacc[m*2 + rh];
            #pragma unroll
            for (int nt = 0; nt < 4; nt++) {
                uint32_t o = h2(O[m][nt][rh*2 + 0] * rl, O[m][nt][rh*2 + 1] * rl);
                *(uint32_t*)&ctxh[grow*DD + h*DH + nt*8 + 2*t4] = o;
            }
        }
}

// ---------------------------------------------------------------------------

extern "C" void kernel_launch(void* const* d_in, const int* in_sizes, int n_in,
                              void* d_out, int out_size)
{
    const float* x   = (const float*)d_in[0];
    const float* Wq  = (const float*)d_in[1];
    const float* bq  = (const float*)d_in[2];
    const float* Wk  = (const float*)d_in[3];
    const float* bk  = (const float*)d_in[4];
    const float* Wv  = (const float*)d_in[5];
    const float* bv  = (const float*)d_in[6];
    const float* Wo  = (const float*)d_in[7];
    const float* bo  = (const float*)d_in[8];
    const float* Wfc = (const float*)d_in[9];
    const float* bfc = (const float*)d_in[10];
    float* out = (float*)d_out;

    float *q, *k, *bc;
    __half *xh, *wh, *wch, *qh, *kh, *vt, *ctxh;
    float2 *sqq, *sqk;
    cudaGetSymbolAddress((void**)&q,    g_q);
    cudaGetSymbolAddress((void**)&k,    g_k);
    cudaGetSymbolAddress((void**)&xh,   g_xh);
    cudaGetSymbolAddress((void**)&wh,   g_wh);
    cudaGetSymbolAddress((void**)&wch,  g_wch);
    cudaGetSymbolAddress((void**)&qh,   g_qh);
    cudaGetSymbolAddress((void**)&kh,   g_kh);
    cudaGetSymbolAddress((void**)&vt,   g_vt);
    cudaGetSymbolAddress((void**)&ctxh, g_ctxh);
    cudaGetSymbolAddress((void**)&sqq,  g_sqq);
    cudaGetSymbolAddress((void**)&sqk,  g_sqk);
    cudaGetSymbolAddress((void**)&bc,   g_bc);

    // [0] fp16 conversions (x + Wq/Wk/Wv) in one launch
    conv_kernel<<<1216, 256>>>(x, Wq, Wk, Wv, xh, wh);

    // [1] Q/K/V projections (V written directly as transposed fp16)
    dim3 qkvgrid(DD/64, NROWS/64, 3);
    gemm16_qkv<<<qkvgrid, 128>>>(xh, wh, bq, bk, bv, q, k, vt);

    // [2] expmap0 (q,k -> fp16 + constants), fast-math
    dim3 egrid(NROWS, 2);
    expmap_kernel<<<egrid, 256>>>(q, k, qh, kh, sqq, sqk);

    // [3] attention (profiled slot)
    dim3 agrid(SS/128, HH, BB);
    attn_kernel<<<agrid, 128>>>(qh, kh, vt, sqq, sqk, ctxh);

    // [4,5] combined output weights + bias
    wcomb_kernel<<<DD, DD>>>(Wfc, Wo, wch);
    bcomb_kernel<<<1, DD>>>(Wfc, bo, bfc, bc);

    // [6] fused output projection + fc
    dim3 ogrid(DD/64, NROWS/64);
    gemm16_one<<<ogrid, 128>>>(ctxh, wch, bc, out);
}